// round 1
// baseline (speedup 1.0000x reference)
#include <cuda_runtime.h>
#include <math.h>

#define Bq 2
#define Lq 1536
#define Dq 1024
#define Hq 8
#define Cq 2048
#define DPHq 256
#define Mq (Bq*Lq)   /* 3072 */

// ---------------- scratch (static device globals; no allocation) ----------------
__device__ float d_xln[(size_t)Mq*Dq];
__device__ float d_y[(size_t)Mq*4096];      // [x1 | x2], ld 4096
__device__ float d_qk[(size_t)Mq*Cq];       // silu(conv(x1))
__device__ float d_proj[(size_t)Mq*4096];   // per-head [q(256)|k(256)] * 8 heads
__device__ float d_v[(size_t)Mq*Cq];
__device__ float d_gates[(size_t)Mq*16];
__device__ float d_g[16*Lq];
__device__ float d_M[16*Lq];
__device__ float d_enm[16*Lq];
__device__ float d_xm[(size_t)Mq*Cq];
__device__ float d_cwt[(size_t)4*Cq*Cq];    // conv_w transposed: [k][co][ci]
__device__ float d_wqkT[Hq*512*256];        // [h][o][i]
__device__ float d_wvT[Hq*256*256];         // [h][o][i]

// ---------------- prep: weight transposes ----------------
__global__ void prep_convw(const float* __restrict__ cw, float* __restrict__ cwt){
    long idx = (long)blockIdx.x*256 + threadIdx.x;
    if (idx >= (long)4*Cq*Cq) return;
    int k  = (int)(idx >> 22);
    long rem = idx & ((1L<<22)-1);
    int co = (int)(rem >> 11), ci = (int)(rem & 2047);
    cwt[idx] = cw[(((long)co<<11) + ci)*4 + k];
}

__global__ void prep_w(const float* __restrict__ wqk, const float* __restrict__ wv,
                       float* __restrict__ wqkT, float* __restrict__ wvT){
    int idx = blockIdx.x*256 + threadIdx.x;
    if (idx < Hq*512*256){
        int h = idx/(512*256); int r = idx%(512*256); int o = r/256; int i = r%256;
        wqkT[idx] = wqk[h*131072 + i*512 + o];
    } else {
        int j = idx - Hq*512*256;
        if (j < Hq*256*256){
            int h = j/65536; int r = j%65536; int o = r/256; int i = r%256;
            wvT[j] = wv[h*65536 + i*256 + o];
        }
    }
}

// ---------------- LayerNorm on x ----------------
__global__ __launch_bounds__(256) void ln_kernel(const float* __restrict__ x,
        const float* __restrict__ w, const float* __restrict__ bb, float* __restrict__ o){
    int m = blockIdx.x, t = threadIdx.x;
    __shared__ float s1[256], s2[256];
    float v[4]; float s = 0.f, q = 0.f;
    #pragma unroll
    for (int u=0;u<4;u++){ v[u] = x[(long)m*Dq + t + u*256]; s += v[u]; q += v[u]*v[u]; }
    s1[t] = s; s2[t] = q; __syncthreads();
    for (int off=128; off; off>>=1){
        if (t < off){ s1[t] += s1[t+off]; s2[t] += s2[t+off]; }
        __syncthreads();
    }
    float mu = s1[0]*(1.f/1024.f);
    float var = s2[0]*(1.f/1024.f) - mu*mu;
    float rs = rsqrtf(var + 1e-5f);
    #pragma unroll
    for (int u=0;u<4;u++){ int c = t + u*256; o[(long)m*Dq + c] = (v[u]-mu)*rs*w[c] + bb[c]; }
}

// ---------------- generic NT SGEMM 128x128x8, multi-tap, epilogues ----------------
struct GemmP {
    const float* A; const float* Bt; float* C;
    const float* bias; const float* add;
    int K, lda, ldb, ldc, ldadd, epi, ntaps;
    long aZ, bZ, cZ, biasZ;
    long aTap[4], bTap[4];
};

__global__ __launch_bounds__(256) void sgemm_nt(GemmP p){
    const int BM=128, BN=128, BK=8, TM=8, TN=8;
    __shared__ float As[BK*BM];
    __shared__ float Bs[BK*BN];
    int tid = threadIdx.x;
    const float* Ab = p.A + blockIdx.z*p.aZ + (long)blockIdx.y*BM*p.lda;
    const float* Bb = p.Bt + blockIdx.z*p.bZ + (long)blockIdx.x*BN*p.ldb;
    int trow = tid >> 4, tcol = tid & 15;
    int ir = tid >> 1, ic = (tid & 1)*4;
    float acc[TM][TN] = {};
    for (int tp=0; tp<p.ntaps; tp++){
        const float* A = Ab + p.aTap[tp];
        const float* B = Bb + p.bTap[tp];
        for (int k0=0; k0<p.K; k0+=BK){
            float4 a4 = *(const float4*)(A + (long)ir*p.lda + k0 + ic);
            float4 b4 = *(const float4*)(B + (long)ir*p.ldb + k0 + ic);
            As[(ic+0)*BM+ir]=a4.x; As[(ic+1)*BM+ir]=a4.y; As[(ic+2)*BM+ir]=a4.z; As[(ic+3)*BM+ir]=a4.w;
            Bs[(ic+0)*BN+ir]=b4.x; Bs[(ic+1)*BN+ir]=b4.y; Bs[(ic+2)*BN+ir]=b4.z; Bs[(ic+3)*BN+ir]=b4.w;
            __syncthreads();
            #pragma unroll
            for (int kk=0; kk<BK; kk++){
                float ra[TM], rb[TN];
                #pragma unroll
                for (int i=0;i<TM;i++) ra[i] = As[kk*BM + trow*TM + i];
                #pragma unroll
                for (int j=0;j<TN;j++) rb[j] = Bs[kk*BN + tcol*TN + j];
                #pragma unroll
                for (int i=0;i<TM;i++)
                    #pragma unroll
                    for (int j=0;j<TN;j++) acc[i][j] += ra[i]*rb[j];
            }
            __syncthreads();
        }
    }
    float* C = p.C + blockIdx.z*p.cZ;
    const float* bias = p.bias ? (p.bias + blockIdx.z*p.biasZ) : (const float*)0;
    long m0 = (long)blockIdx.y*BM + trow*TM;
    int n0 = blockIdx.x*BN + tcol*TN;
    #pragma unroll
    for (int i=0;i<TM;i++){
        long m = m0 + i;
        #pragma unroll
        for (int j=0;j<TN;j++){
            int n = n0 + j;
            float val = acc[i][j];
            if (p.epi >= 1) val += bias[n];
            if (p.epi == 2){ float sg = 1.f/(1.f + expf(-val)); val *= sg; }
            if (p.epi == 3) val += p.add[m*p.ldadd + n];
            C[m*p.ldc + n] = val;
        }
    }
}

// ---------------- gates: (3072 x 16) = qkv(6144) . wif^T + bif ----------------
__global__ __launch_bounds__(256) void gates_kernel(const float* __restrict__ proj,
        const float* __restrict__ vb, const float* __restrict__ wif,
        const float* __restrict__ bif, float* __restrict__ gates){
    __shared__ float As[16*128];
    __shared__ float Ws[128*17];
    int m0 = blockIdx.x*16;
    int tid = threadIdx.x;
    int r = tid >> 4, g = tid & 15;
    float acc = 0.f;
    for (int j0=0; j0<6144; j0+=128){
        __syncthreads();
        for (int e=tid; e<2048; e+=256){
            int jj = e & 127, rr = e >> 7;
            int j = j0 + jj;
            int hh = j/768, t = j - hh*768;
            long m = m0 + rr;
            float v = (t < 512) ? proj[m*4096 + hh*512 + t]
                                : vb[m*2048 + hh*256 + (t-512)];
            As[rr*128 + jj] = v;
        }
        for (int e=tid; e<2048; e+=256){
            int jj = e & 127, gg = e >> 7;
            Ws[jj*17 + gg] = wif[(long)gg*6144 + j0 + jj];
        }
        __syncthreads();
        #pragma unroll 8
        for (int j=0;j<128;j++) acc += As[r*128 + j]*Ws[j*17 + g];
    }
    gates[(long)(m0+r)*16 + g] = acc + bif[g];
}

// ---------------- per-(b,h) scans: f_c cumsum, prefix max of g ----------------
__global__ __launch_bounds__(512) void scan_kernel(const float* __restrict__ gates,
        float* __restrict__ ga, float* __restrict__ Ma, float* __restrict__ ea){
    int bh = blockIdx.x, b = bh >> 3, h = bh & 7;
    int t = threadIdx.x;
    __shared__ float sd[512];
    long base = (long)b*Lq;
    float ls[3], fc[3];
    #pragma unroll
    for (int u=0;u<3;u++){
        int l = t*3 + u;
        float f = gates[(base + l)*16 + 8 + h];
        ls[u] = (f >= 0.f) ? -log1pf(expf(-f)) : (f - log1pf(expf(f)));
    }
    float tot = ls[0] + ls[1] + ls[2];
    sd[t] = tot;
    __syncthreads();
    for (int off=1; off<512; off<<=1){
        float add = (t >= off) ? sd[t-off] : 0.f;
        __syncthreads();
        sd[t] += add;
        __syncthreads();
    }
    float excl = (t > 0) ? sd[t-1] : 0.f;
    fc[0] = excl + ls[0]; fc[1] = fc[0] + ls[1]; fc[2] = fc[1] + ls[2];
    __syncthreads();
    float gv[3], pm[3];
    #pragma unroll
    for (int u=0;u<3;u++){
        int l = t*3 + u;
        float ig = gates[(base + l)*16 + h];
        gv[u] = expf(ig) - fc[u];
    }
    pm[0] = gv[0]; pm[1] = fmaxf(pm[0], gv[1]); pm[2] = fmaxf(pm[1], gv[2]);
    sd[t] = pm[2];
    __syncthreads();
    for (int off=1; off<512; off<<=1){
        float add = (t >= off) ? sd[t-off] : -3.4e38f;
        __syncthreads();
        sd[t] = fmaxf(sd[t], add);
        __syncthreads();
    }
    float exm = (t > 0) ? sd[t-1] : -3.4e38f;
    #pragma unroll
    for (int u=0;u<3;u++){
        int l = t*3 + u;
        float Ml = fmaxf(exm, pm[u]);
        ga[(long)bh*Lq + l] = gv[u];
        Ma[(long)bh*Lq + l] = Ml;
        ea[(long)bh*Lq + l] = expf(-fc[u] - Ml);
    }
}

// ---------------- causal mLSTM attention + head LN + gating epilogue ----------------
// grid: (Lq/32, B*H). 256 threads. Writes xm = (LN(h)+skip*qk) * silu(x2)
__global__ __launch_bounds__(256) void attn_kernel(const float* __restrict__ proj,
        const float* __restrict__ vb, const float* __restrict__ qk,
        const float* __restrict__ y, const float* __restrict__ ga,
        const float* __restrict__ Ma, const float* __restrict__ ea,
        const float* __restrict__ skip, const float* __restrict__ hnw,
        float* __restrict__ xm){
    __shared__ float Qs[256*33];  // [kd][o], q pre-scaled by 1/16
    __shared__ float KV[64*33];   // Kc [kd][i] (padded 33) / Vc [i*64+d]
    __shared__ float Cs[32*33];
    __shared__ float gs[32], Ms[32], en[32], bs[32], nrm[32];
    int bh = blockIdx.y, qt = blockIdx.x;
    int b = bh >> 3, h = bh & 7;
    long mbase = (long)b*Lq;
    int o0 = qt*32;
    int tid = threadIdx.x;
    int ty = tid >> 5, tx = tid & 31;
    int sy = tid >> 4, sx = tid & 15;

    for (int e=tid; e<32*256; e+=256){
        int kd = e & 255, o = e >> 8;
        Qs[kd*33 + o] = proj[(mbase + o0 + o)*4096 + h*512 + kd] * 0.0625f;
    }
    if (tid < 32){
        Ms[tid] = Ma[(long)bh*Lq + o0 + tid];
        en[tid] = ea[(long)bh*Lq + o0 + tid];
        bs[tid] = 0.f;
    }
    float hacc[4][8] = {};
    __syncthreads();

    for (int it=0; it<=qt; ++it){
        int i0 = it*32;
        if (tid < 32) gs[tid] = ga[(long)bh*Lq + i0 + tid];
        float S00=0.f, S01=0.f, S10=0.f, S11=0.f;
        for (int kc=0; kc<4; kc++){
            __syncthreads();
            for (int e=tid; e<64*32; e+=256){
                int kd = e & 63, i = e >> 6;
                KV[kd*33 + i] = proj[(mbase + i0 + i)*4096 + h*512 + 256 + kc*64 + kd];
            }
            __syncthreads();
            #pragma unroll 8
            for (int kd=0; kd<64; kd++){
                float q0 = Qs[(kc*64+kd)*33 + sy*2];
                float q1 = Qs[(kc*64+kd)*33 + sy*2 + 1];
                float k0 = KV[kd*33 + sx*2];
                float k1 = KV[kd*33 + sx*2 + 1];
                S00 += q0*k0; S01 += q0*k1; S10 += q1*k0; S11 += q1*k1;
            }
        }
        __syncthreads();
        bool dg = (it == qt);
        {
            int ol0 = sy*2, il0 = sx*2;
            float w;
            w = (dg && il0   > ol0  ) ? 0.f : expf(gs[il0  ] - Ms[ol0  ]);
            Cs[ ol0   *33 + il0  ] = S00 * w;
            w = (dg && il0+1 > ol0  ) ? 0.f : expf(gs[il0+1] - Ms[ol0  ]);
            Cs[ ol0   *33 + il0+1] = S01 * w;
            w = (dg && il0   > ol0+1) ? 0.f : expf(gs[il0  ] - Ms[ol0+1]);
            Cs[(ol0+1)*33 + il0  ] = S10 * w;
            w = (dg && il0+1 > ol0+1) ? 0.f : expf(gs[il0+1] - Ms[ol0+1]);
            Cs[(ol0+1)*33 + il0+1] = S11 * w;
        }
        __syncthreads();
        if (tid < 32){
            float s = 0.f;
            #pragma unroll 8
            for (int i2=0;i2<32;i2++) s += Cs[tid*33 + i2];
            bs[tid] += s;
        }
        for (int cc=0; cc<4; cc++){
            __syncthreads();
            for (int e=tid; e<2048; e+=256){
                int dd = e & 63, i = e >> 6;
                KV[i*64 + dd] = vb[(mbase + i0 + i)*2048 + h*256 + cc*64 + dd];
            }
            __syncthreads();
            #pragma unroll 4
            for (int i=0;i<32;i++){
                float v0 = KV[i*64 + tx], v1 = KV[i*64 + 32 + tx];
                #pragma unroll
                for (int r=0;r<4;r++){
                    float cv = Cs[(ty*4+r)*33 + i];
                    hacc[r][2*cc]   += cv*v0;
                    hacc[r][2*cc+1] += cv*v1;
                }
            }
        }
        __syncthreads();
    }

    if (tid < 32) nrm[tid] = fmaxf(fabsf(bs[tid]), en[tid]);
    __syncthreads();
    #pragma unroll
    for (int r=0;r<4;r++){
        int ol = ty*4 + r;
        float inv = 1.f / nrm[ol];
        float yv[8]; float s = 0.f, s2 = 0.f;
        #pragma unroll
        for (int j=0;j<8;j++){ yv[j] = hacc[r][j]*inv; s += yv[j]; s2 += yv[j]*yv[j]; }
        #pragma unroll
        for (int off=16; off; off>>=1){
            s  += __shfl_xor_sync(0xffffffff, s,  off);
            s2 += __shfl_xor_sync(0xffffffff, s2, off);
        }
        float mu = s*(1.f/256.f);
        float var = s2*(1.f/256.f) - mu*mu;
        float rstd = rsqrtf(var + 1e-5f);
        long m = mbase + o0 + ol;
        #pragma unroll
        for (int j=0;j<8;j++){
            int d = j*32 + tx;
            float hv = (yv[j] - mu)*rstd*hnw[d];
            int col = h*256 + d;
            float x1o = hv + skip[col]*qk[m*2048 + col];
            float x2v = y[m*4096 + 2048 + col];
            float sg = 1.f/(1.f + expf(-x2v));
            xm[m*2048 + col] = x1o * (x2v*sg);
        }
    }
}

// ---------------- host ----------------
extern "C" void kernel_launch(void* const* d_in, const int* in_sizes, int n_in,
                              void* d_out, int out_size){
    const float* x      = (const float*)d_in[0];
    const float* ln_w   = (const float*)d_in[1];
    const float* ln_b   = (const float*)d_in[2];
    const float* w1     = (const float*)d_in[3];
    const float* b1     = (const float*)d_in[4];
    const float* conv_w = (const float*)d_in[5];
    const float* conv_b = (const float*)d_in[6];
    const float* skip   = (const float*)d_in[7];
    const float* wqk    = (const float*)d_in[8];
    const float* bqk    = (const float*)d_in[9];
    const float* wv     = (const float*)d_in[10];
    const float* bv     = (const float*)d_in[11];
    const float* wif    = (const float*)d_in[12];
    const float* bif    = (const float*)d_in[13];
    const float* hn_w   = (const float*)d_in[14];
    const float* w2     = (const float*)d_in[15];
    const float* b2     = (const float*)d_in[16];
    float* out = (float*)d_out;

    float *xln, *y, *qkb, *proj, *vbuf, *gates, *gA, *MA, *eA, *xm, *cwt, *wqkT, *wvT;
    cudaGetSymbolAddress((void**)&xln,  d_xln);
    cudaGetSymbolAddress((void**)&y,    d_y);
    cudaGetSymbolAddress((void**)&qkb,  d_qk);
    cudaGetSymbolAddress((void**)&proj, d_proj);
    cudaGetSymbolAddress((void**)&vbuf, d_v);
    cudaGetSymbolAddress((void**)&gates,d_gates);
    cudaGetSymbolAddress((void**)&gA,   d_g);
    cudaGetSymbolAddress((void**)&MA,   d_M);
    cudaGetSymbolAddress((void**)&eA,   d_enm);
    cudaGetSymbolAddress((void**)&xm,   d_xm);
    cudaGetSymbolAddress((void**)&cwt,  d_cwt);
    cudaGetSymbolAddress((void**)&wqkT, d_wqkT);
    cudaGetSymbolAddress((void**)&wvT,  d_wvT);

    // weight prep
    prep_convw<<<(int)(((long)4*Cq*Cq + 255)/256), 256>>>(conv_w, cwt);
    prep_w<<<(Hq*512*256 + Hq*256*256 + 255)/256, 256>>>(wqk, wv, wqkT, wvT);

    // LN(x)
    ln_kernel<<<Mq, 256>>>(x, ln_w, ln_b, xln);

    // y = LN(x) @ w1^T + b1
    {
        GemmP p = {};
        p.A = xln; p.Bt = w1; p.C = y; p.bias = b1;
        p.K = 1024; p.lda = 1024; p.ldb = 1024; p.ldc = 4096;
        p.epi = 1; p.ntaps = 1;
        sgemm_nt<<<dim3(4096/128, Mq/128, 1), 256>>>(p);
    }

    // qk = silu(conv(x1))  — conv is over the *batch* axis (literal ref translation)
    for (int b=0;b<Bq;b++){
        GemmP p = {};
        p.A = y; p.Bt = cwt; p.C = qkb + (long)b*Lq*Cq; p.bias = conv_b;
        p.K = Cq; p.lda = 4096; p.ldb = Cq; p.ldc = Cq; p.epi = 2;
        int nt = 0;
        for (int k=0;k<4;k++){
            int jb = b + k - 3;
            if (jb >= 0){
                p.aTap[nt] = (long)jb*Lq*4096;
                p.bTap[nt] = (long)k*Cq*Cq;
                nt++;
            }
        }
        p.ntaps = nt;
        sgemm_nt<<<dim3(Cq/128, Lq/128, 1), 256>>>(p);
    }

    // per-head proj = qk_h @ wqk_h + bqk   (q|k)
    {
        GemmP p = {};
        p.A = qkb; p.Bt = wqkT; p.C = proj; p.bias = bqk;
        p.K = 256; p.lda = 2048; p.ldb = 256; p.ldc = 4096;
        p.aZ = 256; p.bZ = (long)512*256; p.cZ = 512; p.biasZ = 512;
        p.epi = 1; p.ntaps = 1;
        sgemm_nt<<<dim3(512/128, Mq/128, Hq), 256>>>(p);
    }
    // per-head v = x1_h @ wv_h + bv
    {
        GemmP p = {};
        p.A = y; p.Bt = wvT; p.C = vbuf; p.bias = bv;
        p.K = 256; p.lda = 4096; p.ldb = 256; p.ldc = 2048;
        p.aZ = 256; p.bZ = (long)256*256; p.cZ = 256; p.biasZ = 256;
        p.epi = 1; p.ntaps = 1;
        sgemm_nt<<<dim3(256/128, Mq/128, Hq), 256>>>(p);
    }

    gates_kernel<<<Mq/16, 256>>>(proj, vbuf, wif, bif, gates);
    scan_kernel<<<Bq*Hq, 512>>>(gates, gA, MA, eA);

    attn_kernel<<<dim3(Lq/32, Bq*Hq), 256>>>(proj, vbuf, qkb, y, gA, MA, eA,
                                             skip, hn_w, xm);

    // out = xm @ w2^T + b2 + x
    {
        GemmP p = {};
        p.A = xm; p.Bt = w2; p.C = out; p.bias = b2; p.add = x;
        p.K = Cq; p.lda = 2048; p.ldb = 2048; p.ldc = 1024; p.ldadd = 1024;
        p.epi = 3; p.ntaps = 1;
        sgemm_nt<<<dim3(1024/128, Mq/128, 1), 256>>>(p);
    }
}

// round 4
// speedup vs baseline: 1.4883x; 1.4883x over previous
#include <cuda_runtime.h>
#include <cuda_bf16.h>
#include <math.h>
#include <stdint.h>

#define Bq 2
#define Lq 1536
#define Dq 1024
#define Hq 8
#define Cq 2048
#define DPHq 256
#define Mq (Bq*Lq)   /* 3072 */

typedef __nv_bfloat16 bf16;

// ---------------- scratch (static device globals; no allocation) ----------------
__device__ __align__(128) bf16  d_xlnh[(size_t)Mq*Dq],  d_xlnl[(size_t)Mq*Dq];
__device__ __align__(128) float d_y[(size_t)Mq*4096];
__device__ __align__(128) bf16  d_x1h[(size_t)Mq*Cq],  d_x1l[(size_t)Mq*Cq];
__device__ __align__(128) float d_qk[(size_t)Mq*Cq];
__device__ __align__(128) bf16  d_qkh[(size_t)Mq*Cq],  d_qkl[(size_t)Mq*Cq];
__device__ __align__(128) float d_proj[(size_t)Mq*4096];
__device__ __align__(128) float d_v[(size_t)Mq*Cq];
__device__ __align__(128) bf16  d_xmh[(size_t)Mq*Cq],  d_xml[(size_t)Mq*Cq];
__device__ float d_gates[(size_t)Mq*16];
__device__ float d_g[16*Lq];
__device__ float d_M[16*Lq];
__device__ float d_enm[16*Lq];
__device__ __align__(128) bf16  d_w1h[4096*1024],  d_w1l[4096*1024];
__device__ __align__(128) bf16  d_cwth[(size_t)4*Cq*Cq], d_cwtl[(size_t)4*Cq*Cq];
__device__ __align__(128) bf16  d_wqkTh[Hq*512*256], d_wqkTl[Hq*512*256];
__device__ __align__(128) bf16  d_wvTh[Hq*256*256],  d_wvTl[Hq*256*256];
__device__ __align__(128) bf16  d_w2h[1024*2048],  d_w2l[1024*2048];

// ---------------- helpers (baseline PTX only: sm_80-level features) ----------------
__device__ __forceinline__ uint32_t smem_u32(const void* p){
    return (uint32_t)__cvta_generic_to_shared(p);
}
__device__ __forceinline__ void cp16(uint32_t dst, const void* src){
    asm volatile("cp.async.cg.shared.global [%0], [%1], 16;" :: "r"(dst), "l"(src));
}
__device__ __forceinline__ void cp_commit(){ asm volatile("cp.async.commit_group;" ::: "memory"); }
__device__ __forceinline__ void cp_wait0(){ asm volatile("cp.async.wait_group 0;" ::: "memory"); }
__device__ __forceinline__ void cp_wait1(){ asm volatile("cp.async.wait_group 1;" ::: "memory"); }

__device__ __forceinline__ void ldsm_x4(uint32_t* r, uint32_t addr){
    asm volatile("ldmatrix.sync.aligned.m8n8.x4.shared.b16 {%0,%1,%2,%3}, [%4];"
                 : "=r"(r[0]), "=r"(r[1]), "=r"(r[2]), "=r"(r[3]) : "r"(addr));
}
__device__ __forceinline__ void mma16816(float* d, const uint32_t* a, const uint32_t* b){
    asm volatile(
        "mma.sync.aligned.m16n8k16.row.col.f32.bf16.bf16.f32 "
        "{%0,%1,%2,%3}, {%4,%5,%6,%7}, {%8,%9}, {%0,%1,%2,%3};"
        : "+f"(d[0]), "+f"(d[1]), "+f"(d[2]), "+f"(d[3])
        : "r"(a[0]), "r"(a[1]), "r"(a[2]), "r"(a[3]), "r"(b[0]), "r"(b[1]));
}
__device__ __forceinline__ void split_bf(float v, bf16& hi, bf16& lo){
    hi = __float2bfloat16(v);
    lo = __float2bfloat16(v - __bfloat162float(hi));
}

// ---------------- prep kernels ----------------
__global__ void split_plain(const float* __restrict__ w, bf16* __restrict__ h,
                            bf16* __restrict__ l, long n){
    long i = (long)blockIdx.x*256 + threadIdx.x;
    if (i >= n) return;
    bf16 hi, lo; split_bf(w[i], hi, lo);
    h[i] = hi; l[i] = lo;
}
__global__ void prep_cwt(const float* __restrict__ cw, bf16* __restrict__ h, bf16* __restrict__ l){
    long idx = (long)blockIdx.x*256 + threadIdx.x;
    if (idx >= (long)4*Cq*Cq) return;
    int k  = (int)(idx >> 22);
    long rem = idx & ((1L<<22)-1);
    int co = (int)(rem >> 11), ci = (int)(rem & 2047);
    bf16 hi, lo; split_bf(cw[(((long)co<<11) + ci)*4 + k], hi, lo);
    h[idx] = hi; l[idx] = lo;
}
__global__ void prep_wqkv(const float* __restrict__ wqk, const float* __restrict__ wv,
                          bf16* __restrict__ qh, bf16* __restrict__ ql,
                          bf16* __restrict__ vh, bf16* __restrict__ vl){
    int idx = blockIdx.x*256 + threadIdx.x;
    if (idx < Hq*512*256){
        int hh = idx/(512*256); int r = idx%(512*256); int o = r/256; int i = r%256;
        bf16 hi, lo; split_bf(wqk[hh*131072 + i*512 + o], hi, lo);
        qh[idx] = hi; ql[idx] = lo;
    } else {
        int j = idx - Hq*512*256;
        if (j < Hq*256*256){
            int hh = j/65536; int r = j%65536; int o = r/256; int i = r%256;
            bf16 hi, lo; split_bf(wv[hh*65536 + i*256 + o], hi, lo);
            vh[j] = hi; vl[j] = lo;
        }
    }
}

// ---------------- LayerNorm on x -> bf16 hi/lo ----------------
__global__ __launch_bounds__(256) void ln_kernel(const float* __restrict__ x,
        const float* __restrict__ w, const float* __restrict__ bb,
        bf16* __restrict__ oh, bf16* __restrict__ ol){
    int m = blockIdx.x, t = threadIdx.x;
    __shared__ float s1[256], s2[256];
    float v[4]; float s = 0.f, q = 0.f;
    #pragma unroll
    for (int u=0;u<4;u++){ v[u] = x[(long)m*Dq + t + u*256]; s += v[u]; q += v[u]*v[u]; }
    s1[t] = s; s2[t] = q; __syncthreads();
    for (int off=128; off; off>>=1){
        if (t < off){ s1[t] += s1[t+off]; s2[t] += s2[t+off]; }
        __syncthreads();
    }
    float mu = s1[0]*(1.f/1024.f);
    float var = s2[0]*(1.f/1024.f) - mu*mu;
    float rs = rsqrtf(var + 1e-5f);
    #pragma unroll
    for (int u=0;u<4;u++){
        int c = t + u*256;
        float val = (v[u]-mu)*rs*w[c] + bb[c];
        bf16 hi, lo; split_bf(val, hi, lo);
        oh[(long)m*Dq + c] = hi; ol[(long)m*Dq + c] = lo;
    }
}

// ---------------- bf16x3 mma.sync GEMM: C = A @ B^T (NT, K-major) ----------------
struct G5P {
    const bf16 *Ah, *Al, *Bh, *Bl;
    float* Cf;
    bf16 *Oh, *Ol;
    const float* bias; const float* add;
    int K, lda, ldb, ldc, ldo, ldadd, epi, ntaps, splitNmax;
    long aZ, bZ, cZ, biasZ;
    long aTap[2], bTap[2];
};

// smem: 2 stages x 4 tiles(Ah,Al,Bh,Bl) x (128 rows x 80B) = 81920B
// epilogue reuses it as float[128][132]
#define TILE_B   10240
#define STAGE_B  40960

__global__ __launch_bounds__(256, 1) void hgemm(G5P p){
    extern __shared__ char sm[];
    int tid = threadIdx.x;
    int warp = tid >> 5, lane = tid & 31;
    int wm = warp >> 2, wn = warp & 3;     // 2 x 4 warp grid; warp tile 64x32

    long m0 = (long)blockIdx.y*128;
    int  n0 = blockIdx.x*128;
    long aoff = (long)blockIdx.z*p.aZ + m0*p.lda;
    long boff = (long)blockIdx.z*p.bZ + (long)n0*p.ldb;
    int cpt = p.K >> 5;               // chunks of 32 per tap
    int nch = p.ntaps * cpt;

    uint32_t smb = smem_u32(sm);
    float acc[4][4][4] = {};

    // ---- chunk loader (cp.async) ----
    auto loadChunk = [&](int c){
        int tap = c / cpt;
        int k0  = (c - tap*cpt) << 5;
        uint32_t stg = smb + (c & 1)*STAGE_B;
        const bf16* bases[4] = { p.Ah + aoff + p.aTap[tap] + k0,
                                 p.Al + aoff + p.aTap[tap] + k0,
                                 p.Bh + boff + p.bTap[tap] + k0,
                                 p.Bl + boff + p.bTap[tap] + k0 };
        long lds_[4] = { p.lda, p.lda, p.ldb, p.ldb };
        #pragma unroll
        for (int t=0; t<4; t++){
            const bf16* base = bases[t];
            long ld = lds_[t];
            #pragma unroll
            for (int j = tid; j < 512; j += 256){
                int row = j >> 2, ch = j & 3;
                cp16(stg + t*TILE_B + row*80 + ch*16, base + (long)row*ld + ch*8);
            }
        }
    };

    loadChunk(0); cp_commit();

    for (int c=0; c<nch; c++){
        if (c+1 < nch){ loadChunk(c+1); cp_commit(); cp_wait1(); }
        else cp_wait0();
        __syncthreads();

        uint32_t stg = smb + (c & 1)*STAGE_B;
        uint32_t aH = stg, aL = stg + TILE_B, bH = stg + 2*TILE_B, bL = stg + 3*TILE_B;

        int lr = lane & 15, lcs = lane >> 4;            // A ldmatrix lane map
        int gb = lane >> 3, bnr = lane & 7;             // B ldmatrix lane map
        int rowA = wm*64 + lr;
        int rowB = wn*32 + ((gb >> 1) << 3) + bnr;

        #pragma unroll
        for (int ks=0; ks<2; ks++){
            uint32_t ahf[4][4], alf[4][4], bhf[4][2], blf[4][2];
            uint32_t aoffb = (uint32_t)((rowA*5 + ks*2 + lcs) * 16);
            #pragma unroll
            for (int mt=0; mt<4; mt++){
                ldsm_x4(ahf[mt], aH + aoffb + mt*1280);
                ldsm_x4(alf[mt], aL + aoffb + mt*1280);
            }
            uint32_t boffb = (uint32_t)((rowB*5 + ks*2 + (gb & 1)) * 16);
            uint32_t t4[4];
            #pragma unroll
            for (int np=0; np<2; np++){
                ldsm_x4(t4, bH + boffb + np*1280);
                bhf[np*2][0]=t4[0]; bhf[np*2][1]=t4[1]; bhf[np*2+1][0]=t4[2]; bhf[np*2+1][1]=t4[3];
                ldsm_x4(t4, bL + boffb + np*1280);
                blf[np*2][0]=t4[0]; blf[np*2][1]=t4[1]; blf[np*2+1][0]=t4[2]; blf[np*2+1][1]=t4[3];
            }
            #pragma unroll
            for (int mt=0; mt<4; mt++)
                #pragma unroll
                for (int nt=0; nt<4; nt++){
                    mma16816(acc[mt][nt], ahf[mt], bhf[nt]);
                    mma16816(acc[mt][nt], ahf[mt], blf[nt]);
                    mma16816(acc[mt][nt], alf[mt], bhf[nt]);
                }
        }
        __syncthreads();
    }

    // ---- epilogue: stage via smem, coalesced global writes ----
    float* eps = (float*)sm;
    #pragma unroll
    for (int mt=0; mt<4; mt++){
        int r0 = wm*64 + mt*16 + (lane >> 2);
        #pragma unroll
        for (int nt=0; nt<4; nt++){
            int c0 = wn*32 + nt*8 + (lane & 3)*2;
            eps[r0*132 + c0]       = acc[mt][nt][0];
            eps[r0*132 + c0 + 1]   = acc[mt][nt][1];
            eps[(r0+8)*132 + c0]   = acc[mt][nt][2];
            eps[(r0+8)*132 + c0+1] = acc[mt][nt][3];
        }
    }
    __syncthreads();

    const float* bias = p.bias ? (p.bias + (long)blockIdx.z*p.biasZ) : (const float*)0;
    long czo = (long)blockIdx.z * p.cZ;
    for (int j = tid; j < 128*128; j += 256){
        int rr = j >> 7, cc = j & 127;
        long m = m0 + rr;
        int n = n0 + cc;
        float val = eps[rr*132 + cc];
        if (bias) val += bias[n];
        if (p.epi & 2){ val = val / (1.f + expf(-val)); }
        if (p.epi & 4){ val += p.add[m*p.ldadd + n]; }
        if (p.Cf) p.Cf[m*p.ldc + czo + n] = val;
        if (n < p.splitNmax){
            bf16 hi, lo; split_bf(val, hi, lo);
            p.Oh[m*p.ldo + n] = hi;
            p.Ol[m*p.ldo + n] = lo;
        }
    }
}

// ---------------- gates ----------------
__global__ __launch_bounds__(256) void gates_kernel(const float* __restrict__ proj,
        const float* __restrict__ vb, const float* __restrict__ wif,
        const float* __restrict__ bif, float* __restrict__ gates){
    __shared__ float As[16*128];
    __shared__ float Ws[128*17];
    int m0 = blockIdx.x*16;
    int tid = threadIdx.x;
    int r = tid >> 4, g = tid & 15;
    float acc = 0.f;
    for (int j0=0; j0<6144; j0+=128){
        __syncthreads();
        for (int e=tid; e<2048; e+=256){
            int jj = e & 127, rr = e >> 7;
            int j = j0 + jj;
            int hh = j/768, t = j - hh*768;
            long m = m0 + rr;
            float v = (t < 512) ? proj[m*4096 + hh*512 + t]
                                : vb[m*2048 + hh*256 + (t-512)];
            As[rr*128 + jj] = v;
        }
        for (int e=tid; e<2048; e+=256){
            int jj = e & 127, gg = e >> 7;
            Ws[jj*17 + gg] = wif[(long)gg*6144 + j0 + jj];
        }
        __syncthreads();
        #pragma unroll 8
        for (int j=0;j<128;j++) acc += As[r*128 + j]*Ws[j*17 + g];
    }
    gates[(long)(m0+r)*16 + g] = acc + bif[g];
}

// ---------------- per-(b,h) scans ----------------
__global__ __launch_bounds__(512) void scan_kernel(const float* __restrict__ gates,
        float* __restrict__ ga, float* __restrict__ Ma, float* __restrict__ ea){
    int bh = blockIdx.x, b = bh >> 3, h = bh & 7;
    int t = threadIdx.x;
    __shared__ float sd[512];
    long base = (long)b*Lq;
    float ls[3], fc[3];
    #pragma unroll
    for (int u=0;u<3;u++){
        int l = t*3 + u;
        float f = gates[(base + l)*16 + 8 + h];
        ls[u] = (f >= 0.f) ? -log1pf(expf(-f)) : (f - log1pf(expf(f)));
    }
    float tot = ls[0] + ls[1] + ls[2];
    sd[t] = tot;
    __syncthreads();
    for (int off=1; off<512; off<<=1){
        float add = (t >= off) ? sd[t-off] : 0.f;
        __syncthreads();
        sd[t] += add;
        __syncthreads();
    }
    float excl = (t > 0) ? sd[t-1] : 0.f;
    fc[0] = excl + ls[0]; fc[1] = fc[0] + ls[1]; fc[2] = fc[1] + ls[2];
    __syncthreads();
    float gv[3], pm[3];
    #pragma unroll
    for (int u=0;u<3;u++){
        int l = t*3 + u;
        float ig = gates[(base + l)*16 + h];
        gv[u] = expf(ig) - fc[u];
    }
    pm[0] = gv[0]; pm[1] = fmaxf(pm[0], gv[1]); pm[2] = fmaxf(pm[1], gv[2]);
    sd[t] = pm[2];
    __syncthreads();
    for (int off=1; off<512; off<<=1){
        float add = (t >= off) ? sd[t-off] : -3.4e38f;
        __syncthreads();
        sd[t] = fmaxf(sd[t], add);
        __syncthreads();
    }
    float exm = (t > 0) ? sd[t-1] : -3.4e38f;
    #pragma unroll
    for (int u=0;u<3;u++){
        int l = t*3 + u;
        float Ml = fmaxf(exm, pm[u]);
        ga[(long)bh*Lq + l] = gv[u];
        Ma[(long)bh*Lq + l] = Ml;
        ea[(long)bh*Lq + l] = expf(-fc[u] - Ml);
    }
}

// ---------------- causal mLSTM attention + head LN + gating epilogue ----------------
__global__ __launch_bounds__(256) void attn_kernel(const float* __restrict__ proj,
        const float* __restrict__ vb, const float* __restrict__ qk,
        const float* __restrict__ y, const float* __restrict__ ga,
        const float* __restrict__ Ma, const float* __restrict__ ea,
        const float* __restrict__ skip, const float* __restrict__ hnw,
        bf16* __restrict__ xmh, bf16* __restrict__ xml){
    __shared__ float Qs[256*33];
    __shared__ float KV[64*33];
    __shared__ float Cs[32*33];
    __shared__ float gs[32], Ms[32], en[32], bs[32], nrm[32];
    int bh = blockIdx.y, qt = blockIdx.x;
    int b = bh >> 3, h = bh & 7;
    long mbase = (long)b*Lq;
    int o0 = qt*32;
    int tid = threadIdx.x;
    int ty = tid >> 5, tx = tid & 31;
    int sy = tid >> 4, sx = tid & 15;

    for (int e=tid; e<32*256; e+=256){
        int kd = e & 255, o = e >> 8;
        Qs[kd*33 + o] = proj[(mbase + o0 + o)*4096 + h*512 + kd] * 0.0625f;
    }
    if (tid < 32){
        Ms[tid] = Ma[(long)bh*Lq + o0 + tid];
        en[tid] = ea[(long)bh*Lq + o0 + tid];
        bs[tid] = 0.f;
    }
    float hacc[4][8] = {};
    __syncthreads();

    for (int it=0; it<=qt; ++it){
        int i0 = it*32;
        if (tid < 32) gs[tid] = ga[(long)bh*Lq + i0 + tid];
        float S00=0.f, S01=0.f, S10=0.f, S11=0.f;
        for (int kc=0; kc<4; kc++){
            __syncthreads();
            for (int e=tid; e<64*32; e+=256){
                int kd = e & 63, i = e >> 6;
                KV[kd*33 + i] = proj[(mbase + i0 + i)*4096 + h*512 + 256 + kc*64 + kd];
            }
            __syncthreads();
            #pragma unroll 8
            for (int kd=0; kd<64; kd++){
                float q0 = Qs[(kc*64+kd)*33 + sy*2];
                float q1 = Qs[(kc*64+kd)*33 + sy*2 + 1];
                float k0 = KV[kd*33 + sx*2];
                float k1 = KV[kd*33 + sx*2 + 1];
                S00 += q0*k0; S01 += q0*k1; S10 += q1*k0; S11 += q1*k1;
            }
        }
        __syncthreads();
        bool dg = (it == qt);
        {
            int ol0 = sy*2, il0 = sx*2;
            float w;
            w = (dg && il0   > ol0  ) ? 0.f : expf(gs[il0  ] - Ms[ol0  ]);
            Cs[ ol0   *33 + il0  ] = S00 * w;
            w = (dg && il0+1 > ol0  ) ? 0.f : expf(gs[il0+1] - Ms[ol0  ]);
            Cs[ ol0   *33 + il0+1] = S01 * w;
            w = (dg && il0   > ol0+1) ? 0.f : expf(gs[il0  ] - Ms[ol0+1]);
            Cs[(ol0+1)*33 + il0  ] = S10 * w;
            w = (dg && il0+1 > ol0+1) ? 0.f : expf(gs[il0+1] - Ms[ol0+1]);
            Cs[(ol0+1)*33 + il0+1] = S11 * w;
        }
        __syncthreads();
        if (tid < 32){
            float s = 0.f;
            #pragma unroll 8
            for (int i2=0;i2<32;i2++) s += Cs[tid*33 + i2];
            bs[tid] += s;
        }
        for (int cc=0; cc<4; cc++){
            __syncthreads();
            for (int e=tid; e<2048; e+=256){
                int dd = e & 63, i = e >> 6;
                KV[i*64 + dd] = vb[(mbase + i0 + i)*2048 + h*256 + cc*64 + dd];
            }
            __syncthreads();
            #pragma unroll 4
            for (int i=0;i<32;i++){
                float v0 = KV[i*64 + tx], v1 = KV[i*64 + 32 + tx];
                #pragma unroll
                for (int r=0;r<4;r++){
                    float cv = Cs[(ty*4+r)*33 + i];
                    hacc[r][2*cc]   += cv*v0;
                    hacc[r][2*cc+1] += cv*v1;
                }
            }
        }
        __syncthreads();
    }

    if (tid < 32) nrm[tid] = fmaxf(fabsf(bs[tid]), en[tid]);
    __syncthreads();
    #pragma unroll
    for (int r=0;r<4;r++){
        int ol = ty*4 + r;
        float inv = 1.f / nrm[ol];
        float yv[8]; float s = 0.f, s2 = 0.f;
        #pragma unroll
        for (int j=0;j<8;j++){ yv[j] = hacc[r][j]*inv; s += yv[j]; s2 += yv[j]*yv[j]; }
        #pragma unroll
        for (int off=16; off; off>>=1){
            s  += __shfl_xor_sync(0xffffffff, s,  off);
            s2 += __shfl_xor_sync(0xffffffff, s2, off);
        }
        float mu = s*(1.f/256.f);
        float var = s2*(1.f/256.f) - mu*mu;
        float rstd = rsqrtf(var + 1e-5f);
        long m = mbase + o0 + ol;
        #pragma unroll
        for (int j=0;j<8;j++){
            int d = j*32 + tx;
            float hv = (yv[j] - mu)*rstd*hnw[d];
            int col = h*256 + d;
            float x1o = hv + skip[col]*qk[m*2048 + col];
            float x2v = y[m*4096 + 2048 + col];
            float sg = 1.f/(1.f + expf(-x2v));
            float res = x1o * (x2v*sg);
            bf16 hi, lo; split_bf(res, hi, lo);
            xmh[m*2048 + col] = hi;
            xml[m*2048 + col] = lo;
        }
    }
}

// ---------------- host ----------------
extern "C" void kernel_launch(void* const* d_in, const int* in_sizes, int n_in,
                              void* d_out, int out_size){
    const float* x      = (const float*)d_in[0];
    const float* ln_w   = (const float*)d_in[1];
    const float* ln_b   = (const float*)d_in[2];
    const float* w1     = (const float*)d_in[3];
    const float* b1     = (const float*)d_in[4];
    const float* conv_w = (const float*)d_in[5];
    const float* conv_b = (const float*)d_in[6];
    const float* skip   = (const float*)d_in[7];
    const float* wqk    = (const float*)d_in[8];
    const float* bqk    = (const float*)d_in[9];
    const float* wv     = (const float*)d_in[10];
    const float* bv     = (const float*)d_in[11];
    const float* wif    = (const float*)d_in[12];
    const float* bif    = (const float*)d_in[13];
    const float* hn_w   = (const float*)d_in[14];
    const float* w2     = (const float*)d_in[15];
    const float* b2     = (const float*)d_in[16];
    float* out = (float*)d_out;

    bf16 *xlnh,*xlnl,*x1h,*x1l,*qkh,*qkl,*xmh,*xml;
    bf16 *w1h,*w1l,*cwth,*cwtl,*wqkTh,*wqkTl,*wvTh,*wvTl,*w2h,*w2l;
    float *y,*qkb,*proj,*vbuf,*gates,*gA,*MA,*eA;
    cudaGetSymbolAddress((void**)&xlnh, d_xlnh);  cudaGetSymbolAddress((void**)&xlnl, d_xlnl);
    cudaGetSymbolAddress((void**)&y,    d_y);
    cudaGetSymbolAddress((void**)&x1h,  d_x1h);   cudaGetSymbolAddress((void**)&x1l,  d_x1l);
    cudaGetSymbolAddress((void**)&qkb,  d_qk);
    cudaGetSymbolAddress((void**)&qkh,  d_qkh);   cudaGetSymbolAddress((void**)&qkl,  d_qkl);
    cudaGetSymbolAddress((void**)&proj, d_proj);
    cudaGetSymbolAddress((void**)&vbuf, d_v);
    cudaGetSymbolAddress((void**)&xmh,  d_xmh);   cudaGetSymbolAddress((void**)&xml,  d_xml);
    cudaGetSymbolAddress((void**)&gates,d_gates);
    cudaGetSymbolAddress((void**)&gA,   d_g);
    cudaGetSymbolAddress((void**)&MA,   d_M);
    cudaGetSymbolAddress((void**)&eA,   d_enm);
    cudaGetSymbolAddress((void**)&w1h,  d_w1h);   cudaGetSymbolAddress((void**)&w1l,  d_w1l);
    cudaGetSymbolAddress((void**)&cwth, d_cwth);  cudaGetSymbolAddress((void**)&cwtl, d_cwtl);
    cudaGetSymbolAddress((void**)&wqkTh,d_wqkTh); cudaGetSymbolAddress((void**)&wqkTl,d_wqkTl);
    cudaGetSymbolAddress((void**)&wvTh, d_wvTh);  cudaGetSymbolAddress((void**)&wvTl, d_wvTl);
    cudaGetSymbolAddress((void**)&w2h,  d_w2h);   cudaGetSymbolAddress((void**)&w2l,  d_w2l);

    cudaFuncSetAttribute(hgemm, cudaFuncAttributeMaxDynamicSharedMemorySize, 81920);

    // weight prep (hi/lo bf16 splits)
    split_plain<<<(4096*1024 + 255)/256, 256>>>(w1, w1h, w1l, (long)4096*1024);
    split_plain<<<(1024*2048 + 255)/256, 256>>>(w2, w2h, w2l, (long)1024*2048);
    prep_cwt<<<(int)(((long)4*Cq*Cq + 255)/256), 256>>>(conv_w, cwth, cwtl);
    prep_wqkv<<<(Hq*512*256 + Hq*256*256 + 255)/256, 256>>>(wqk, wv, wqkTh, wqkTl, wvTh, wvTl);

    // LN(x) -> bf16 hi/lo
    ln_kernel<<<Mq, 256>>>(x, ln_w, ln_b, xlnh, xlnl);

    // y = LN(x) @ w1^T + b1 : f32 y (all cols) + bf16 split of x1 (cols < 2048)
    {
        G5P p = {};
        p.Ah = xlnh; p.Al = xlnl; p.Bh = w1h; p.Bl = w1l;
        p.Cf = y; p.Oh = x1h; p.Ol = x1l; p.bias = b1;
        p.K = 1024; p.lda = 1024; p.ldb = 1024; p.ldc = 4096; p.ldo = 2048;
        p.epi = 1; p.ntaps = 1; p.splitNmax = 2048;
        hgemm<<<dim3(32, 24, 1), 256, 81920>>>(p);
    }

    // qk = silu(conv(x1)) — conv over batch axis; multi-tap accumulate
    for (int b=0; b<Bq; b++){
        G5P p = {};
        p.Ah = x1h; p.Al = x1l; p.Bh = cwth; p.Bl = cwtl;
        p.Cf = qkb + (long)b*Lq*Cq;
        p.Oh = qkh + (long)b*Lq*Cq; p.Ol = qkl + (long)b*Lq*Cq;
        p.bias = conv_b;
        p.K = Cq; p.lda = Cq; p.ldb = Cq; p.ldc = Cq; p.ldo = Cq;
        p.epi = 1|2; p.splitNmax = Cq;
        int nt = 0;
        for (int k=0;k<4;k++){
            int jb = b + k - 3;
            if (jb >= 0){
                p.aTap[nt] = (long)jb*Lq*Cq;
                p.bTap[nt] = (long)k*Cq*Cq;
                nt++;
            }
        }
        p.ntaps = nt;
        hgemm<<<dim3(16, 12, 1), 256, 81920>>>(p);
    }

    // per-head proj = qk_h @ wqk_h + bqk
    {
        G5P p = {};
        p.Ah = qkh; p.Al = qkl; p.Bh = wqkTh; p.Bl = wqkTl;
        p.Cf = proj; p.bias = bqk;
        p.K = 256; p.lda = 2048; p.ldb = 256; p.ldc = 4096;
        p.aZ = 256; p.bZ = (long)512*256; p.cZ = 512; p.biasZ = 512;
        p.epi = 1; p.ntaps = 1; p.splitNmax = 0;
        hgemm<<<dim3(4, 24, Hq), 256, 81920>>>(p);
    }
    // per-head v = x1_h @ wv_h + bv
    {
        G5P p = {};
        p.Ah = x1h; p.Al = x1l; p.Bh = wvTh; p.Bl = wvTl;
        p.Cf = vbuf; p.bias = bv;
        p.K = 256; p.lda = 2048; p.ldb = 256; p.ldc = 2048;
        p.aZ = 256; p.bZ = (long)256*256; p.cZ = 256; p.biasZ = 256;
        p.epi = 1; p.ntaps = 1; p.splitNmax = 0;
        hgemm<<<dim3(2, 24, Hq), 256, 81920>>>(p);
    }

    gates_kernel<<<Mq/16, 256>>>(proj, vbuf, wif, bif, gates);
    scan_kernel<<<Bq*Hq, 512>>>(gates, gA, MA, eA);

    attn_kernel<<<dim3(Lq/32, Bq*Hq), 256>>>(proj, vbuf, qkb, y, gA, MA, eA,
                                             skip, hn_w, xmh, xml);

    // out = xm @ w2^T + b2 + x
    {
        G5P p = {};
        p.Ah = xmh; p.Al = xml; p.Bh = w2h; p.Bl = w2l;
        p.Cf = out; p.bias = b2; p.add = x;
        p.K = Cq; p.lda = 2048; p.ldb = 2048; p.ldc = 1024; p.ldadd = 1024;
        p.epi = 1|4; p.ntaps = 1; p.splitNmax = 0;
        hgemm<<<dim3(8, 24, 1), 256, 81920>>>(p);
    }
}

// round 5
// speedup vs baseline: 2.3436x; 1.5747x over previous
#include <cuda_runtime.h>
#include <cuda_bf16.h>
#include <math.h>
#include <stdint.h>

#define Bq 2
#define Lq 1536
#define Dq 1024
#define Hq 8
#define Cq 2048
#define DPHq 256
#define Mq (Bq*Lq)   /* 3072 */

typedef __nv_bfloat16 bf16;

// ---------------- scratch (static device globals; no allocation) ----------------
__device__ __align__(128) bf16  d_xlnh[(size_t)Mq*Dq],  d_xlnl[(size_t)Mq*Dq];
__device__ __align__(128) float d_y[(size_t)Mq*4096];
__device__ __align__(128) bf16  d_x1h[(size_t)Mq*Cq],  d_x1l[(size_t)Mq*Cq];
__device__ __align__(128) float d_qk[(size_t)Mq*Cq];
__device__ __align__(128) bf16  d_qkh[(size_t)Mq*Cq],  d_qkl[(size_t)Mq*Cq];
__device__ __align__(128) float d_proj[(size_t)Mq*4096];
__device__ __align__(128) bf16  d_pjh[(size_t)Mq*4096], d_pjl[(size_t)Mq*4096];
__device__ __align__(128) float d_v[(size_t)Mq*Cq];
__device__ __align__(128) bf16  d_vbh[(size_t)Mq*Cq],  d_vbl[(size_t)Mq*Cq];
__device__ __align__(128) bf16  d_xmh[(size_t)Mq*Cq],  d_xml[(size_t)Mq*Cq];
__device__ float d_gates[(size_t)Mq*16];
__device__ float d_g[16*Lq];
__device__ float d_M[16*Lq];
__device__ float d_enm[16*Lq];
__device__ __align__(128) bf16  d_w1h[4096*1024],  d_w1l[4096*1024];
__device__ __align__(128) bf16  d_cwth[(size_t)4*Cq*Cq], d_cwtl[(size_t)4*Cq*Cq];
__device__ __align__(128) bf16  d_wqkTh[Hq*512*256], d_wqkTl[Hq*512*256];
__device__ __align__(128) bf16  d_wvTh[Hq*256*256],  d_wvTl[Hq*256*256];
__device__ __align__(128) bf16  d_w2h[1024*2048],  d_w2l[1024*2048];

// ---------------- helpers (baseline PTX only: sm_80-level features) ----------------
__device__ __forceinline__ uint32_t smem_u32(const void* p){
    return (uint32_t)__cvta_generic_to_shared(p);
}
__device__ __forceinline__ void cp16(uint32_t dst, const void* src){
    asm volatile("cp.async.cg.shared.global [%0], [%1], 16;" :: "r"(dst), "l"(src));
}
__device__ __forceinline__ void cp_commit(){ asm volatile("cp.async.commit_group;" ::: "memory"); }
__device__ __forceinline__ void cp_wait0(){ asm volatile("cp.async.wait_group 0;" ::: "memory"); }
__device__ __forceinline__ void cp_wait1(){ asm volatile("cp.async.wait_group 1;" ::: "memory"); }

__device__ __forceinline__ void ldsm_x4(uint32_t* r, uint32_t addr){
    asm volatile("ldmatrix.sync.aligned.m8n8.x4.shared.b16 {%0,%1,%2,%3}, [%4];"
                 : "=r"(r[0]), "=r"(r[1]), "=r"(r[2]), "=r"(r[3]) : "r"(addr));
}
__device__ __forceinline__ void ldsm_x4t(uint32_t* r, uint32_t addr){
    asm volatile("ldmatrix.sync.aligned.m8n8.x4.trans.shared.b16 {%0,%1,%2,%3}, [%4];"
                 : "=r"(r[0]), "=r"(r[1]), "=r"(r[2]), "=r"(r[3]) : "r"(addr));
}
__device__ __forceinline__ void mma16816(float* d, const uint32_t* a, const uint32_t* b){
    asm volatile(
        "mma.sync.aligned.m16n8k16.row.col.f32.bf16.bf16.f32 "
        "{%0,%1,%2,%3}, {%4,%5,%6,%7}, {%8,%9}, {%0,%1,%2,%3};"
        : "+f"(d[0]), "+f"(d[1]), "+f"(d[2]), "+f"(d[3])
        : "r"(a[0]), "r"(a[1]), "r"(a[2]), "r"(a[3]), "r"(b[0]), "r"(b[1]));
}
__device__ __forceinline__ void split_bf(float v, bf16& hi, bf16& lo){
    hi = __float2bfloat16(v);
    lo = __float2bfloat16(v - __bfloat162float(hi));
}
__device__ __forceinline__ uint32_t pack2(bf16 a, bf16 b){
    uint16_t ua = *(uint16_t*)&a, ub = *(uint16_t*)&b;
    return (uint32_t)ua | ((uint32_t)ub << 16);
}

// ---------------- prep kernels ----------------
__global__ void split_plain(const float* __restrict__ w, bf16* __restrict__ h,
                            bf16* __restrict__ l, long n){
    long i = (long)blockIdx.x*256 + threadIdx.x;
    if (i >= n) return;
    bf16 hi, lo; split_bf(w[i], hi, lo);
    h[i] = hi; l[i] = lo;
}
__global__ void prep_cwt(const float* __restrict__ cw, bf16* __restrict__ h, bf16* __restrict__ l){
    long idx = (long)blockIdx.x*256 + threadIdx.x;
    if (idx >= (long)4*Cq*Cq) return;
    int k  = (int)(idx >> 22);
    long rem = idx & ((1L<<22)-1);
    int co = (int)(rem >> 11), ci = (int)(rem & 2047);
    bf16 hi, lo; split_bf(cw[(((long)co<<11) + ci)*4 + k], hi, lo);
    h[idx] = hi; l[idx] = lo;
}
__global__ void prep_wqkv(const float* __restrict__ wqk, const float* __restrict__ wv,
                          bf16* __restrict__ qh, bf16* __restrict__ ql,
                          bf16* __restrict__ vh, bf16* __restrict__ vl){
    int idx = blockIdx.x*256 + threadIdx.x;
    if (idx < Hq*512*256){
        int hh = idx/(512*256); int r = idx%(512*256); int o = r/256; int i = r%256;
        bf16 hi, lo; split_bf(wqk[hh*131072 + i*512 + o], hi, lo);
        qh[idx] = hi; ql[idx] = lo;
    } else {
        int j = idx - Hq*512*256;
        if (j < Hq*256*256){
            int hh = j/65536; int r = j%65536; int o = r/256; int i = r%256;
            bf16 hi, lo; split_bf(wv[hh*65536 + i*256 + o], hi, lo);
            vh[j] = hi; vl[j] = lo;
        }
    }
}

// ---------------- LayerNorm on x -> bf16 hi/lo ----------------
__global__ __launch_bounds__(256) void ln_kernel(const float* __restrict__ x,
        const float* __restrict__ w, const float* __restrict__ bb,
        bf16* __restrict__ oh, bf16* __restrict__ ol){
    int m = blockIdx.x, t = threadIdx.x;
    __shared__ float s1[256], s2[256];
    float v[4]; float s = 0.f, q = 0.f;
    #pragma unroll
    for (int u=0;u<4;u++){ v[u] = x[(long)m*Dq + t + u*256]; s += v[u]; q += v[u]*v[u]; }
    s1[t] = s; s2[t] = q; __syncthreads();
    for (int off=128; off; off>>=1){
        if (t < off){ s1[t] += s1[t+off]; s2[t] += s2[t+off]; }
        __syncthreads();
    }
    float mu = s1[0]*(1.f/1024.f);
    float var = s2[0]*(1.f/1024.f) - mu*mu;
    float rs = rsqrtf(var + 1e-5f);
    #pragma unroll
    for (int u=0;u<4;u++){
        int c = t + u*256;
        float val = (v[u]-mu)*rs*w[c] + bb[c];
        bf16 hi, lo; split_bf(val, hi, lo);
        oh[(long)m*Dq + c] = hi; ol[(long)m*Dq + c] = lo;
    }
}

// ---------------- bf16x3 mma.sync GEMM: C = A @ B^T (NT, K-major) ----------------
struct G5P {
    const bf16 *Ah, *Al, *Bh, *Bl;
    float* Cf;
    bf16 *Oh, *Ol;
    const float* bias; const float* add;
    int K, lda, ldb, ldc, ldo, ldadd, epi, ntaps, splitNmax;
    long aZ, bZ, cZ, biasZ, oZ;
    long aTap[2], bTap[2];
};

#define TILE_B   10240
#define STAGE_B  40960

__global__ __launch_bounds__(256, 1) void hgemm(G5P p){
    extern __shared__ char sm[];
    int tid = threadIdx.x;
    int warp = tid >> 5, lane = tid & 31;
    int wm = warp >> 2, wn = warp & 3;     // 2 x 4 warp grid; warp tile 64x32

    long m0 = (long)blockIdx.y*128;
    int  n0 = blockIdx.x*128;
    long aoff = (long)blockIdx.z*p.aZ + m0*p.lda;
    long boff = (long)blockIdx.z*p.bZ + (long)n0*p.ldb;
    int cpt = p.K >> 5;               // chunks of 32 per tap
    int nch = p.ntaps * cpt;

    uint32_t smb = smem_u32(sm);
    float acc[4][4][4] = {};

    auto loadChunk = [&](int c){
        int tap = c / cpt;
        int k0  = (c - tap*cpt) << 5;
        uint32_t stg = smb + (c & 1)*STAGE_B;
        const bf16* bases[4] = { p.Ah + aoff + p.aTap[tap] + k0,
                                 p.Al + aoff + p.aTap[tap] + k0,
                                 p.Bh + boff + p.bTap[tap] + k0,
                                 p.Bl + boff + p.bTap[tap] + k0 };
        long lds_[4] = { p.lda, p.lda, p.ldb, p.ldb };
        #pragma unroll
        for (int t=0; t<4; t++){
            const bf16* base = bases[t];
            long ld = lds_[t];
            #pragma unroll
            for (int j = tid; j < 512; j += 256){
                int row = j >> 2, ch = j & 3;
                cp16(stg + t*TILE_B + row*80 + ch*16, base + (long)row*ld + ch*8);
            }
        }
    };

    loadChunk(0); cp_commit();

    for (int c=0; c<nch; c++){
        if (c+1 < nch){ loadChunk(c+1); cp_commit(); cp_wait1(); }
        else cp_wait0();
        __syncthreads();

        uint32_t stg = smb + (c & 1)*STAGE_B;
        uint32_t aH = stg, aL = stg + TILE_B, bH = stg + 2*TILE_B, bL = stg + 3*TILE_B;

        int lr = lane & 15, lcs = lane >> 4;
        int gb = lane >> 3, bnr = lane & 7;
        int rowA = wm*64 + lr;
        int rowB = wn*32 + ((gb >> 1) << 3) + bnr;

        #pragma unroll
        for (int ks=0; ks<2; ks++){
            uint32_t ahf[4][4], alf[4][4], bhf[4][2], blf[4][2];
            uint32_t aoffb = (uint32_t)((rowA*5 + ks*2 + lcs) * 16);
            #pragma unroll
            for (int mt=0; mt<4; mt++){
                ldsm_x4(ahf[mt], aH + aoffb + mt*1280);
                ldsm_x4(alf[mt], aL + aoffb + mt*1280);
            }
            uint32_t boffb = (uint32_t)((rowB*5 + ks*2 + (gb & 1)) * 16);
            uint32_t t4[4];
            #pragma unroll
            for (int np=0; np<2; np++){
                ldsm_x4(t4, bH + boffb + np*1280);
                bhf[np*2][0]=t4[0]; bhf[np*2][1]=t4[1]; bhf[np*2+1][0]=t4[2]; bhf[np*2+1][1]=t4[3];
                ldsm_x4(t4, bL + boffb + np*1280);
                blf[np*2][0]=t4[0]; blf[np*2][1]=t4[1]; blf[np*2+1][0]=t4[2]; blf[np*2+1][1]=t4[3];
            }
            #pragma unroll
            for (int mt=0; mt<4; mt++)
                #pragma unroll
                for (int nt=0; nt<4; nt++){
                    mma16816(acc[mt][nt], ahf[mt], bhf[nt]);
                    mma16816(acc[mt][nt], ahf[mt], blf[nt]);
                    mma16816(acc[mt][nt], alf[mt], bhf[nt]);
                }
        }
        __syncthreads();
    }

    float* eps = (float*)sm;
    #pragma unroll
    for (int mt=0; mt<4; mt++){
        int r0 = wm*64 + mt*16 + (lane >> 2);
        #pragma unroll
        for (int nt=0; nt<4; nt++){
            int c0 = wn*32 + nt*8 + (lane & 3)*2;
            eps[r0*132 + c0]       = acc[mt][nt][0];
            eps[r0*132 + c0 + 1]   = acc[mt][nt][1];
            eps[(r0+8)*132 + c0]   = acc[mt][nt][2];
            eps[(r0+8)*132 + c0+1] = acc[mt][nt][3];
        }
    }
    __syncthreads();

    const float* bias = p.bias ? (p.bias + (long)blockIdx.z*p.biasZ) : (const float*)0;
    long czo = (long)blockIdx.z * p.cZ;
    long ozo = (long)blockIdx.z * p.oZ;
    for (int j = tid; j < 128*128; j += 256){
        int rr = j >> 7, cc = j & 127;
        long m = m0 + rr;
        int n = n0 + cc;
        float val = eps[rr*132 + cc];
        if (bias) val += bias[n];
        if (p.epi & 2){ val = val / (1.f + expf(-val)); }
        if (p.epi & 4){ val += p.add[m*p.ldadd + n]; }
        if (p.Cf) p.Cf[m*p.ldc + czo + n] = val;
        if (n < p.splitNmax){
            bf16 hi, lo; split_bf(val, hi, lo);
            p.Oh[m*p.ldo + ozo + n] = hi;
            p.Ol[m*p.ldo + ozo + n] = lo;
        }
    }
}

// ---------------- gates ----------------
__global__ __launch_bounds__(256) void gates_kernel(const float* __restrict__ proj,
        const float* __restrict__ vb, const float* __restrict__ wif,
        const float* __restrict__ bif, float* __restrict__ gates){
    __shared__ float As[16*128];
    __shared__ float Ws[128*17];
    int m0 = blockIdx.x*16;
    int tid = threadIdx.x;
    int r = tid >> 4, g = tid & 15;
    float acc = 0.f;
    for (int j0=0; j0<6144; j0+=128){
        __syncthreads();
        for (int e=tid; e<2048; e+=256){
            int jj = e & 127, rr = e >> 7;
            int j = j0 + jj;
            int hh = j/768, t = j - hh*768;
            long m = m0 + rr;
            float v = (t < 512) ? proj[m*4096 + hh*512 + t]
                                : vb[m*2048 + hh*256 + (t-512)];
            As[rr*128 + jj] = v;
        }
        for (int e=tid; e<2048; e+=256){
            int jj = e & 127, gg = e >> 7;
            Ws[jj*17 + gg] = wif[(long)gg*6144 + j0 + jj];
        }
        __syncthreads();
        #pragma unroll 8
        for (int j=0;j<128;j++) acc += As[r*128 + j]*Ws[j*17 + g];
    }
    gates[(long)(m0+r)*16 + g] = acc + bif[g];
}

// ---------------- per-(b,h) scans ----------------
__global__ __launch_bounds__(512) void scan_kernel(const float* __restrict__ gates,
        float* __restrict__ ga, float* __restrict__ Ma, float* __restrict__ ea){
    int bh = blockIdx.x, b = bh >> 3, h = bh & 7;
    int t = threadIdx.x;
    __shared__ float sd[512];
    long base = (long)b*Lq;
    float ls[3], fc[3];
    #pragma unroll
    for (int u=0;u<3;u++){
        int l = t*3 + u;
        float f = gates[(base + l)*16 + 8 + h];
        ls[u] = (f >= 0.f) ? -log1pf(expf(-f)) : (f - log1pf(expf(f)));
    }
    float tot = ls[0] + ls[1] + ls[2];
    sd[t] = tot;
    __syncthreads();
    for (int off=1; off<512; off<<=1){
        float add = (t >= off) ? sd[t-off] : 0.f;
        __syncthreads();
        sd[t] += add;
        __syncthreads();
    }
    float excl = (t > 0) ? sd[t-1] : 0.f;
    fc[0] = excl + ls[0]; fc[1] = fc[0] + ls[1]; fc[2] = fc[1] + ls[2];
    __syncthreads();
    float gv[3], pm[3];
    #pragma unroll
    for (int u=0;u<3;u++){
        int l = t*3 + u;
        float ig = gates[(base + l)*16 + h];
        gv[u] = expf(ig) - fc[u];
    }
    pm[0] = gv[0]; pm[1] = fmaxf(pm[0], gv[1]); pm[2] = fmaxf(pm[1], gv[2]);
    sd[t] = pm[2];
    __syncthreads();
    for (int off=1; off<512; off<<=1){
        float add = (t >= off) ? sd[t-off] : -3.4e38f;
        __syncthreads();
        sd[t] = fmaxf(sd[t], add);
        __syncthreads();
    }
    float exm = (t > 0) ? sd[t-1] : -3.4e38f;
    #pragma unroll
    for (int u=0;u<3;u++){
        int l = t*3 + u;
        float Ml = fmaxf(exm, pm[u]);
        ga[(long)bh*Lq + l] = gv[u];
        Ma[(long)bh*Lq + l] = Ml;
        ea[(long)bh*Lq + l] = expf(-fc[u] - Ml);
    }
}

// ---------------- tensor-core mLSTM attention + fused epilogue ----------------
// grid (24, 16), block 128. smem: Qh/Ql 64x528 | 2 K bufs | 2 V bufs | E[64]
#define QH_OFF 0
#define QL_OFF 33792
#define KB_OFF 67584
#define VB_OFF 104448
#define E_OFF  141312
#define ATT_SMEM 141568

__global__ __launch_bounds__(128, 1) void attn2(
    const bf16* __restrict__ pjh, const bf16* __restrict__ pjl,
    const bf16* __restrict__ vbh, const bf16* __restrict__ vbl,
    const float* __restrict__ qk, const float* __restrict__ y,
    const float* __restrict__ ga, const float* __restrict__ Ma,
    const float* __restrict__ ea, const float* __restrict__ skip,
    const float* __restrict__ hnw,
    bf16* __restrict__ xmh, bf16* __restrict__ xml)
{
    extern __shared__ char sm[];
    const uint32_t smb = smem_u32(sm);
    float* Esm = (float*)(sm + E_OFF);

    int tid = threadIdx.x, w = tid >> 5, lane = tid & 31;
    int bh = blockIdx.y, b = bh >> 3, h = bh & 7;
    int qt = (int)gridDim.x - 1 - (int)blockIdx.x;
    long mbase = (long)b*Lq;
    int o0 = qt*64;

    int rowg = w*16 + (lane >> 2);
    float F0  = expf(-Ma[(long)bh*Lq + o0 + rowg])     * 0.0625f;
    float F8  = expf(-Ma[(long)bh*Lq + o0 + rowg + 8]) * 0.0625f;
    float en0 = ea[(long)bh*Lq + o0 + rowg];
    float en8 = ea[(long)bh*Lq + o0 + rowg + 8];

    // Q load (own group)
    for (int j = tid; j < 4096; j += 128){
        int t = j >> 11, rem = j & 2047;
        int row = rem >> 5, c = rem & 31;
        const bf16* src = (t ? pjl : pjh) + (mbase + o0 + row)*4096 + h*512 + c*8;
        cp16(smb + (t ? QL_OFF : QH_OFF) + row*528 + c*16, src);
    }
    cp_commit();

    int total = (qt + 1)*8;
    auto issueItem = [&](int idx){
        int it = idx >> 3, sub = idx & 7;
        long i0 = (long)it*64;
        uint32_t buf; const bf16 *sh, *sl; long ldg, goff;
        if (sub < 4){ buf = smb + KB_OFF + (sub & 1)*18432; sh = pjh; sl = pjl; ldg = 4096; goff = h*512 + 256 + sub*64; }
        else        { buf = smb + VB_OFF + (sub & 1)*18432; sh = vbh; sl = vbl; ldg = 2048; goff = h*256 + (sub - 4)*64; }
        for (int j = tid; j < 1024; j += 128){
            int t = j >> 9, rem = j & 511;
            int row = rem >> 3, c8 = rem & 7;
            const bf16* src = (t ? sl : sh) + (mbase + i0 + row)*ldg + goff + c8*8;
            cp16(buf + t*9216 + row*144 + c8*16, src);
        }
    };
    issueItem(0); cp_commit();
    if (total > 1) issueItem(1);
    cp_commit();

    float accH[32][4];
    #pragma unroll
    for (int g=0; g<32; g++){ accH[g][0]=0.f; accH[g][1]=0.f; accH[g][2]=0.f; accH[g][3]=0.f; }
    float sacc[8][4];
    uint32_t pkh[8][2], pkl[8][2];
    float rs0 = 0.f, rs1 = 0.f;

    uint32_t qrow = (uint32_t)((w*16 + (lane & 15))*528 + (lane >> 4)*16);
    int gb = lane >> 3;
    uint32_t krow = (uint32_t)(((((gb >> 1) << 3) + (lane & 7)))*144 + (gb & 1)*16);
    uint32_t vrow = (uint32_t)((lane & 15)*144 + (lane >> 4)*16);

    for (int idx = 0; idx < total; idx++){
        int it = idx >> 3, sub = idx & 7;
        cp_wait1();
        __syncthreads();
        if (sub < 4){
            if (sub == 0){
                if (tid < 64) Esm[tid] = expf(ga[(long)bh*Lq + (long)it*64 + tid]);
                #pragma unroll
                for (int g=0; g<8; g++){ sacc[g][0]=0.f; sacc[g][1]=0.f; sacc[g][2]=0.f; sacc[g][3]=0.f; }
            }
            uint32_t kb = smb + KB_OFF + (sub & 1)*18432;
            #pragma unroll
            for (int ks=0; ks<4; ks++){
                uint32_t qa = qrow + sub*128 + ks*32;
                uint32_t qh4[4], ql4[4];
                ldsm_x4(qh4, smb + QH_OFF + qa);
                ldsm_x4(ql4, smb + QL_OFF + qa);
                #pragma unroll
                for (int kt=0; kt<4; kt++){
                    uint32_t ka = kb + krow + kt*(16*144) + ks*32;
                    uint32_t bh4[4], bl4[4];
                    ldsm_x4(bh4, ka);
                    ldsm_x4(bl4, ka + 9216);
                    mma16816(sacc[kt*2],   qh4, bh4);
                    mma16816(sacc[kt*2],   qh4, bl4);
                    mma16816(sacc[kt*2],   ql4, bh4);
                    mma16816(sacc[kt*2+1], qh4, bh4 + 2);
                    mma16816(sacc[kt*2+1], qh4, bl4 + 2);
                    mma16816(sacc[kt*2+1], ql4, bh4 + 2);
                }
            }
            if (sub == 3){
                bool diag = (it == qt);
                #pragma unroll
                for (int nt=0; nt<8; nt++){
                    int cb = nt*8 + (lane & 3)*2;
                    float e0 = Esm[cb], e1 = Esm[cb+1];
                    float w00 = e0*F0, w01 = e1*F0, w10 = e0*F8, w11 = e1*F8;
                    if (diag){
                        if (cb     > rowg)     w00 = 0.f;
                        if (cb + 1 > rowg)     w01 = 0.f;
                        if (cb     > rowg + 8) w10 = 0.f;
                        if (cb + 1 > rowg + 8) w11 = 0.f;
                    }
                    float c0 = sacc[nt][0]*w00, c1 = sacc[nt][1]*w01;
                    float c2 = sacc[nt][2]*w10, c3 = sacc[nt][3]*w11;
                    rs0 += c0 + c1; rs1 += c2 + c3;
                    bf16 h0,l0,h1,l1;
                    split_bf(c0, h0, l0); split_bf(c1, h1, l1);
                    pkh[nt][0] = pack2(h0, h1); pkl[nt][0] = pack2(l0, l1);
                    split_bf(c2, h0, l0); split_bf(c3, h1, l1);
                    pkh[nt][1] = pack2(h0, h1); pkl[nt][1] = pack2(l0, l1);
                }
            }
        } else {
            int vc = sub - 4;
            uint32_t vbb = smb + VB_OFF + (sub & 1)*18432;
            #pragma unroll
            for (int kk=0; kk<4; kk++){
                uint32_t aH[4] = { pkh[2*kk][0], pkh[2*kk][1], pkh[2*kk+1][0], pkh[2*kk+1][1] };
                uint32_t aL[4] = { pkl[2*kk][0], pkl[2*kk][1], pkl[2*kk+1][0], pkl[2*kk+1][1] };
                #pragma unroll
                for (int np=0; np<4; np++){
                    uint32_t va = vbb + vrow + kk*(16*144) + np*32;
                    uint32_t tH[4], tL[4];
                    ldsm_x4t(tH, va);
                    ldsm_x4t(tL, va + 9216);
                    int g0 = vc*8 + 2*np;
                    mma16816(accH[g0],   aH, tH);
                    mma16816(accH[g0],   aH, tL);
                    mma16816(accH[g0],   aL, tH);
                    mma16816(accH[g0+1], aH, tH + 2);
                    mma16816(accH[g0+1], aH, tL + 2);
                    mma16816(accH[g0+1], aL, tH + 2);
                }
            }
        }
        __syncthreads();
        if (idx + 2 < total) issueItem(idx + 2);
        cp_commit();
    }

    // row sums (quad lanes share rows)
    rs0 += __shfl_xor_sync(0xffffffffu, rs0, 1);
    rs0 += __shfl_xor_sync(0xffffffffu, rs0, 2);
    rs1 += __shfl_xor_sync(0xffffffffu, rs1, 1);
    rs1 += __shfl_xor_sync(0xffffffffu, rs1, 2);
    float inv0 = 1.f / fmaxf(fabsf(rs0), en0);
    float inv1 = 1.f / fmaxf(fabsf(rs1), en8);

    float s0=0.f, q0=0.f, s1=0.f, q1=0.f;
    #pragma unroll
    for (int g=0; g<32; g++){
        float v0 = accH[g][0]*inv0, v1 = accH[g][1]*inv0;
        float v2 = accH[g][2]*inv1, v3 = accH[g][3]*inv1;
        accH[g][0]=v0; accH[g][1]=v1; accH[g][2]=v2; accH[g][3]=v3;
        s0 += v0 + v1; q0 += v0*v0 + v1*v1;
        s1 += v2 + v3; q1 += v2*v2 + v3*v3;
    }
    s0 += __shfl_xor_sync(0xffffffffu, s0, 1); s0 += __shfl_xor_sync(0xffffffffu, s0, 2);
    q0 += __shfl_xor_sync(0xffffffffu, q0, 1); q0 += __shfl_xor_sync(0xffffffffu, q0, 2);
    s1 += __shfl_xor_sync(0xffffffffu, s1, 1); s1 += __shfl_xor_sync(0xffffffffu, s1, 2);
    q1 += __shfl_xor_sync(0xffffffffu, q1, 1); q1 += __shfl_xor_sync(0xffffffffu, q1, 2);
    float mu0 = s0*(1.f/256.f), var0 = q0*(1.f/256.f) - mu0*mu0, rst0 = rsqrtf(var0 + 1e-5f);
    float mu1 = s1*(1.f/256.f), var1 = q1*(1.f/256.f) - mu1*mu1, rst1 = rsqrtf(var1 + 1e-5f);

    long mr0 = mbase + o0 + rowg;
    long mr8 = mr0 + 8;
    #pragma unroll
    for (int g=0; g<32; g++){
        int d0 = g*8 + (lane & 3)*2;
        int col = h*256 + d0;
        float2 hw = *(const float2*)(hnw + d0);
        float2 sk = *(const float2*)(skip + col);
        {
            float2 q2 = *(const float2*)(qk + mr0*2048 + col);
            float2 x2 = *(const float2*)(y + mr0*4096 + 2048 + col);
            float hv0 = (accH[g][0] - mu0)*rst0*hw.x;
            float hv1 = (accH[g][1] - mu0)*rst0*hw.y;
            float a0 = hv0 + sk.x*q2.x, a1 = hv1 + sk.y*q2.y;
            float r0 = a0 * (x2.x / (1.f + expf(-x2.x)));
            float r1 = a1 * (x2.y / (1.f + expf(-x2.y)));
            bf16 hh0,ll0,hh1,ll1; split_bf(r0,hh0,ll0); split_bf(r1,hh1,ll1);
            *(uint32_t*)(xmh + mr0*2048 + col) = pack2(hh0, hh1);
            *(uint32_t*)(xml + mr0*2048 + col) = pack2(ll0, ll1);
        }
        {
            float2 q2 = *(const float2*)(qk + mr8*2048 + col);
            float2 x2 = *(const float2*)(y + mr8*4096 + 2048 + col);
            float hv0 = (accH[g][2] - mu1)*rst1*hw.x;
            float hv1 = (accH[g][3] - mu1)*rst1*hw.y;
            float a0 = hv0 + sk.x*q2.x, a1 = hv1 + sk.y*q2.y;
            float r0 = a0 * (x2.x / (1.f + expf(-x2.x)));
            float r1 = a1 * (x2.y / (1.f + expf(-x2.y)));
            bf16 hh0,ll0,hh1,ll1; split_bf(r0,hh0,ll0); split_bf(r1,hh1,ll1);
            *(uint32_t*)(xmh + mr8*2048 + col) = pack2(hh0, hh1);
            *(uint32_t*)(xml + mr8*2048 + col) = pack2(ll0, ll1);
        }
    }
}

// ---------------- host ----------------
extern "C" void kernel_launch(void* const* d_in, const int* in_sizes, int n_in,
                              void* d_out, int out_size){
    const float* x      = (const float*)d_in[0];
    const float* ln_w   = (const float*)d_in[1];
    const float* ln_b   = (const float*)d_in[2];
    const float* w1     = (const float*)d_in[3];
    const float* b1     = (const float*)d_in[4];
    const float* conv_w = (const float*)d_in[5];
    const float* conv_b = (const float*)d_in[6];
    const float* skip   = (const float*)d_in[7];
    const float* wqk    = (const float*)d_in[8];
    const float* bqk    = (const float*)d_in[9];
    const float* wv     = (const float*)d_in[10];
    const float* bv     = (const float*)d_in[11];
    const float* wif    = (const float*)d_in[12];
    const float* bif    = (const float*)d_in[13];
    const float* hn_w   = (const float*)d_in[14];
    const float* w2     = (const float*)d_in[15];
    const float* b2     = (const float*)d_in[16];
    float* out = (float*)d_out;

    bf16 *xlnh,*xlnl,*x1h,*x1l,*qkh,*qkl,*xmh,*xml,*pjh,*pjl,*vbh,*vbl;
    bf16 *w1h,*w1l,*cwth,*cwtl,*wqkTh,*wqkTl,*wvTh,*wvTl,*w2h,*w2l;
    float *y,*qkb,*proj,*vbuf,*gates,*gA,*MA,*eA;
    cudaGetSymbolAddress((void**)&xlnh, d_xlnh);  cudaGetSymbolAddress((void**)&xlnl, d_xlnl);
    cudaGetSymbolAddress((void**)&y,    d_y);
    cudaGetSymbolAddress((void**)&x1h,  d_x1h);   cudaGetSymbolAddress((void**)&x1l,  d_x1l);
    cudaGetSymbolAddress((void**)&qkb,  d_qk);
    cudaGetSymbolAddress((void**)&qkh,  d_qkh);   cudaGetSymbolAddress((void**)&qkl,  d_qkl);
    cudaGetSymbolAddress((void**)&proj, d_proj);
    cudaGetSymbolAddress((void**)&pjh,  d_pjh);   cudaGetSymbolAddress((void**)&pjl,  d_pjl);
    cudaGetSymbolAddress((void**)&vbuf, d_v);
    cudaGetSymbolAddress((void**)&vbh,  d_vbh);   cudaGetSymbolAddress((void**)&vbl,  d_vbl);
    cudaGetSymbolAddress((void**)&xmh,  d_xmh);   cudaGetSymbolAddress((void**)&xml,  d_xml);
    cudaGetSymbolAddress((void**)&gates,d_gates);
    cudaGetSymbolAddress((void**)&gA,   d_g);
    cudaGetSymbolAddress((void**)&MA,   d_M);
    cudaGetSymbolAddress((void**)&eA,   d_enm);
    cudaGetSymbolAddress((void**)&w1h,  d_w1h);   cudaGetSymbolAddress((void**)&w1l,  d_w1l);
    cudaGetSymbolAddress((void**)&cwth, d_cwth);  cudaGetSymbolAddress((void**)&cwtl, d_cwtl);
    cudaGetSymbolAddress((void**)&wqkTh,d_wqkTh); cudaGetSymbolAddress((void**)&wqkTl,d_wqkTl);
    cudaGetSymbolAddress((void**)&wvTh, d_wvTh);  cudaGetSymbolAddress((void**)&wvTl, d_wvTl);
    cudaGetSymbolAddress((void**)&w2h,  d_w2h);   cudaGetSymbolAddress((void**)&w2l,  d_w2l);

    cudaFuncSetAttribute(hgemm, cudaFuncAttributeMaxDynamicSharedMemorySize, 81920);
    cudaFuncSetAttribute(attn2, cudaFuncAttributeMaxDynamicSharedMemorySize, ATT_SMEM);

    split_plain<<<(4096*1024 + 255)/256, 256>>>(w1, w1h, w1l, (long)4096*1024);
    split_plain<<<(1024*2048 + 255)/256, 256>>>(w2, w2h, w2l, (long)1024*2048);
    prep_cwt<<<(int)(((long)4*Cq*Cq + 255)/256), 256>>>(conv_w, cwth, cwtl);
    prep_wqkv<<<(Hq*512*256 + Hq*256*256 + 255)/256, 256>>>(wqk, wv, wqkTh, wqkTl, wvTh, wvTl);

    ln_kernel<<<Mq, 256>>>(x, ln_w, ln_b, xlnh, xlnl);

    // y = LN(x) @ w1^T + b1 : f32 y + bf16 split of x1 (cols < 2048)
    {
        G5P p = {};
        p.Ah = xlnh; p.Al = xlnl; p.Bh = w1h; p.Bl = w1l;
        p.Cf = y; p.Oh = x1h; p.Ol = x1l; p.bias = b1;
        p.K = 1024; p.lda = 1024; p.ldb = 1024; p.ldc = 4096; p.ldo = 2048;
        p.epi = 1; p.ntaps = 1; p.splitNmax = 2048;
        hgemm<<<dim3(32, 24, 1), 256, 81920>>>(p);
    }

    // qk = silu(conv(x1)) — conv over batch axis; multi-tap accumulate
    for (int b=0; b<Bq; b++){
        G5P p = {};
        p.Ah = x1h; p.Al = x1l; p.Bh = cwth; p.Bl = cwtl;
        p.Cf = qkb + (long)b*Lq*Cq;
        p.Oh = qkh + (long)b*Lq*Cq; p.Ol = qkl + (long)b*Lq*Cq;
        p.bias = conv_b;
        p.K = Cq; p.lda = Cq; p.ldb = Cq; p.ldc = Cq; p.ldo = Cq;
        p.epi = 1|2; p.splitNmax = Cq;
        int nt = 0;
        for (int k=0;k<4;k++){
            int jb = b + k - 3;
            if (jb >= 0){
                p.aTap[nt] = (long)jb*Lq*Cq;
                p.bTap[nt] = (long)k*Cq*Cq;
                nt++;
            }
        }
        p.ntaps = nt;
        hgemm<<<dim3(16, 12, 1), 256, 81920>>>(p);
    }

    // per-head proj = qk_h @ wqk_h + bqk  (f32 for gates + bf16 hi/lo for attention)
    {
        G5P p = {};
        p.Ah = qkh; p.Al = qkl; p.Bh = wqkTh; p.Bl = wqkTl;
        p.Cf = proj; p.Oh = pjh; p.Ol = pjl; p.bias = bqk;
        p.K = 256; p.lda = 2048; p.ldb = 256; p.ldc = 4096; p.ldo = 4096;
        p.aZ = 256; p.bZ = (long)512*256; p.cZ = 512; p.biasZ = 512; p.oZ = 512;
        p.epi = 1; p.ntaps = 1; p.splitNmax = 512;
        hgemm<<<dim3(4, 24, Hq), 256, 81920>>>(p);
    }
    // per-head v = x1_h @ wv_h + bv  (f32 + bf16 hi/lo)
    {
        G5P p = {};
        p.Ah = x1h; p.Al = x1l; p.Bh = wvTh; p.Bl = wvTl;
        p.Cf = vbuf; p.Oh = vbh; p.Ol = vbl; p.bias = bv;
        p.K = 256; p.lda = 2048; p.ldb = 256; p.ldc = 2048; p.ldo = 2048;
        p.aZ = 256; p.bZ = (long)256*256; p.cZ = 256; p.biasZ = 256; p.oZ = 256;
        p.epi = 1; p.ntaps = 1; p.splitNmax = 256;
        hgemm<<<dim3(2, 24, Hq), 256, 81920>>>(p);
    }

    gates_kernel<<<Mq/16, 256>>>(proj, vbuf, wif, bif, gates);
    scan_kernel<<<Bq*Hq, 512>>>(gates, gA, MA, eA);

    attn2<<<dim3(24, 16), 128, ATT_SMEM>>>(pjh, pjl, vbh, vbl, qkb, y,
                                           gA, MA, eA, skip, hn_w, xmh, xml);

    // out = xm @ w2^T + b2 + x
    {
        G5P p = {};
        p.Ah = xmh; p.Al = xml; p.Bh = w2h; p.Bl = w2l;
        p.Cf = out; p.bias = b2; p.add = x;
        p.K = Cq; p.lda = 2048; p.ldb = 2048; p.ldc = 1024; p.ldadd = 1024;
        p.epi = 1|4; p.ntaps = 1; p.splitNmax = 0;
        hgemm<<<dim3(8, 24, 1), 256, 81920>>>(p);
    }
}

// round 6
// speedup vs baseline: 2.5734x; 1.0980x over previous
#include <cuda_runtime.h>
#include <cuda_bf16.h>
#include <math.h>
#include <stdint.h>

#define Bq 2
#define Lq 1536
#define Dq 1024
#define Hq 8
#define Cq 2048
#define DPHq 256
#define Mq (Bq*Lq)   /* 3072 */

typedef __nv_bfloat16 bf16;

// ---------------- scratch (static device globals; no allocation) ----------------
__device__ __align__(128) bf16  d_xlnh[(size_t)Mq*Dq],  d_xlnl[(size_t)Mq*Dq];
__device__ __align__(128) float d_y[(size_t)Mq*4096];
__device__ __align__(128) bf16  d_x1h[(size_t)Mq*Cq],  d_x1l[(size_t)Mq*Cq];
__device__ __align__(128) float d_qk[(size_t)Mq*Cq];
__device__ __align__(128) bf16  d_qkh[(size_t)Mq*Cq],  d_qkl[(size_t)Mq*Cq];
__device__ __align__(128) float d_proj[(size_t)Mq*4096];
__device__ __align__(128) bf16  d_pjh[(size_t)Mq*4096], d_pjl[(size_t)Mq*4096];
__device__ __align__(128) float d_v[(size_t)Mq*Cq];
__device__ __align__(128) bf16  d_vbh[(size_t)Mq*Cq],  d_vbl[(size_t)Mq*Cq];
__device__ __align__(128) bf16  d_xmh[(size_t)Mq*Cq],  d_xml[(size_t)Mq*Cq];
__device__ float d_gates[(size_t)Mq*16];
__device__ float d_g[16*Lq];
__device__ float d_M[16*Lq];
__device__ float d_enm[16*Lq];
__device__ __align__(128) bf16  d_w1h[4096*1024],  d_w1l[4096*1024];
__device__ __align__(128) bf16  d_cwth[(size_t)4*Cq*Cq], d_cwtl[(size_t)4*Cq*Cq];
__device__ __align__(128) bf16  d_wqkTh[Hq*512*256], d_wqkTl[Hq*512*256];
__device__ __align__(128) bf16  d_wvTh[Hq*256*256],  d_wvTl[Hq*256*256];
__device__ __align__(128) bf16  d_w2h[1024*2048],  d_w2l[1024*2048];

// ---------------- helpers ----------------
__device__ __forceinline__ uint32_t smem_u32(const void* p){
    return (uint32_t)__cvta_generic_to_shared(p);
}
__device__ __forceinline__ void cp16(uint32_t dst, const void* src){
    asm volatile("cp.async.cg.shared.global [%0], [%1], 16;" :: "r"(dst), "l"(src));
}
__device__ __forceinline__ void cp_commit(){ asm volatile("cp.async.commit_group;" ::: "memory"); }
__device__ __forceinline__ void cp_wait0(){ asm volatile("cp.async.wait_group 0;" ::: "memory"); }
__device__ __forceinline__ void cp_wait1(){ asm volatile("cp.async.wait_group 1;" ::: "memory"); }
__device__ __forceinline__ void cp_wait2(){ asm volatile("cp.async.wait_group 2;" ::: "memory"); }

__device__ __forceinline__ void ldsm_x4(uint32_t* r, uint32_t addr){
    asm volatile("ldmatrix.sync.aligned.m8n8.x4.shared.b16 {%0,%1,%2,%3}, [%4];"
                 : "=r"(r[0]), "=r"(r[1]), "=r"(r[2]), "=r"(r[3]) : "r"(addr));
}
__device__ __forceinline__ void ldsm_x4t(uint32_t* r, uint32_t addr){
    asm volatile("ldmatrix.sync.aligned.m8n8.x4.trans.shared.b16 {%0,%1,%2,%3}, [%4];"
                 : "=r"(r[0]), "=r"(r[1]), "=r"(r[2]), "=r"(r[3]) : "r"(addr));
}
__device__ __forceinline__ void mma16816(float* d, const uint32_t* a, const uint32_t* b){
    asm volatile(
        "mma.sync.aligned.m16n8k16.row.col.f32.bf16.bf16.f32 "
        "{%0,%1,%2,%3}, {%4,%5,%6,%7}, {%8,%9}, {%0,%1,%2,%3};"
        : "+f"(d[0]), "+f"(d[1]), "+f"(d[2]), "+f"(d[3])
        : "r"(a[0]), "r"(a[1]), "r"(a[2]), "r"(a[3]), "r"(b[0]), "r"(b[1]));
}
__device__ __forceinline__ void split_bf(float v, bf16& hi, bf16& lo){
    hi = __float2bfloat16(v);
    lo = __float2bfloat16(v - __bfloat162float(hi));
}
__device__ __forceinline__ uint32_t pack2(bf16 a, bf16 b){
    uint16_t ua = *(uint16_t*)&a, ub = *(uint16_t*)&b;
    return (uint32_t)ua | ((uint32_t)ub << 16);
}

// ---------------- prep kernels ----------------
__global__ void split_plain(const float* __restrict__ w, bf16* __restrict__ h,
                            bf16* __restrict__ l, long n){
    long i = (long)blockIdx.x*256 + threadIdx.x;
    if (i >= n) return;
    bf16 hi, lo; split_bf(w[i], hi, lo);
    h[i] = hi; l[i] = lo;
}
__global__ void prep_cwt(const float* __restrict__ cw, bf16* __restrict__ h, bf16* __restrict__ l){
    long idx = (long)blockIdx.x*256 + threadIdx.x;
    if (idx >= (long)4*Cq*Cq) return;
    int k  = (int)(idx >> 22);
    long rem = idx & ((1L<<22)-1);
    int co = (int)(rem >> 11), ci = (int)(rem & 2047);
    bf16 hi, lo; split_bf(cw[(((long)co<<11) + ci)*4 + k], hi, lo);
    h[idx] = hi; l[idx] = lo;
}
__global__ void prep_wqkv(const float* __restrict__ wqk, const float* __restrict__ wv,
                          bf16* __restrict__ qh, bf16* __restrict__ ql,
                          bf16* __restrict__ vh, bf16* __restrict__ vl){
    int idx = blockIdx.x*256 + threadIdx.x;
    if (idx < Hq*512*256){
        int hh = idx/(512*256); int r = idx%(512*256); int o = r/256; int i = r%256;
        bf16 hi, lo; split_bf(wqk[hh*131072 + i*512 + o], hi, lo);
        qh[idx] = hi; ql[idx] = lo;
    } else {
        int j = idx - Hq*512*256;
        if (j < Hq*256*256){
            int hh = j/65536; int r = j%65536; int o = r/256; int i = r%256;
            bf16 hi, lo; split_bf(wv[hh*65536 + i*256 + o], hi, lo);
            vh[j] = hi; vl[j] = lo;
        }
    }
}

// ---------------- LayerNorm on x -> bf16 hi/lo ----------------
__global__ __launch_bounds__(256) void ln_kernel(const float* __restrict__ x,
        const float* __restrict__ w, const float* __restrict__ bb,
        bf16* __restrict__ oh, bf16* __restrict__ ol){
    int m = blockIdx.x, t = threadIdx.x;
    __shared__ float s1[256], s2[256];
    float v[4]; float s = 0.f, q = 0.f;
    #pragma unroll
    for (int u=0;u<4;u++){ v[u] = x[(long)m*Dq + t + u*256]; s += v[u]; q += v[u]*v[u]; }
    s1[t] = s; s2[t] = q; __syncthreads();
    for (int off=128; off; off>>=1){
        if (t < off){ s1[t] += s1[t+off]; s2[t] += s2[t+off]; }
        __syncthreads();
    }
    float mu = s1[0]*(1.f/1024.f);
    float var = s2[0]*(1.f/1024.f) - mu*mu;
    float rs = rsqrtf(var + 1e-5f);
    #pragma unroll
    for (int u=0;u<4;u++){
        int c = t + u*256;
        float val = (v[u]-mu)*rs*w[c] + bb[c];
        bf16 hi, lo; split_bf(val, hi, lo);
        oh[(long)m*Dq + c] = hi; ol[(long)m*Dq + c] = lo;
    }
}

// ---------------- bf16x3 mma.sync GEMM: C = A @ B^T (NT, K-major) ----------------
// epi bits: 1=bias, 2=silu, 4=residual add, 8=conv mode (batch-dependent taps)
struct G5P {
    const bf16 *Ah, *Al, *Bh, *Bl;
    float* Cf;
    bf16 *Oh, *Ol;
    const float* bias; const float* add;
    int K, lda, ldb, ldc, ldo, ldadd, epi, ntaps, ntaps2, splitNmax;
    long aZ, bZ, cZ, biasZ, oZ;
    long aTap[2], bTap[2];
    long aTap2[2], bTap2[2];
};

// MT = # of 16-row mma tiles per warp; BM = MT*32 (2x4 warp grid)
// 3-stage pipeline. smem/stage: 2 A tiles (BM*80) + 2 B tiles (128*80)
template<int MT>
__global__ __launch_bounds__(256, 1) void hgemm(G5P p){
    constexpr int BM = MT*32;
    constexpr int TA = BM*80;
    constexpr int TB = 10240;
    constexpr int STG = 2*TA + 2*TB;
    extern __shared__ char sm[];
    int tid = threadIdx.x;
    int warp = tid >> 5, lane = tid & 31;
    int wm = warp >> 2, wn = warp & 3;

    long m0 = (long)blockIdx.y*BM;
    int  n0 = blockIdx.x*128;

    long arow; int ntaps; long aT[2], bT[2];
    if (p.epi & 8){
        int batch = (int)(m0 / Lq);
        arow = m0 - (long)batch*Lq;
        if (batch == 0){ ntaps = p.ntaps;  aT[0]=p.aTap[0];  bT[0]=p.bTap[0];  aT[1]=p.aTap[1];  bT[1]=p.bTap[1]; }
        else           { ntaps = p.ntaps2; aT[0]=p.aTap2[0]; bT[0]=p.bTap2[0]; aT[1]=p.aTap2[1]; bT[1]=p.bTap2[1]; }
    } else {
        arow = m0; ntaps = p.ntaps;
        aT[0]=p.aTap[0]; bT[0]=p.bTap[0]; aT[1]=p.aTap[1]; bT[1]=p.bTap[1];
    }

    long aoff = (long)blockIdx.z*p.aZ + arow*p.lda;
    long boff = (long)blockIdx.z*p.bZ + (long)n0*p.ldb;
    int cpt = p.K >> 5;
    int nch = ntaps * cpt;

    uint32_t smb = smem_u32(sm);
    float acc[MT][4][4] = {};

    auto loadChunk = [&](int c){
        int tap = c / cpt;
        int k0  = (c - tap*cpt) << 5;
        uint32_t stg = smb + (c % 3)*STG;
        const bf16* aB[2] = { p.Ah + aoff + aT[tap] + k0, p.Al + aoff + aT[tap] + k0 };
        #pragma unroll
        for (int t=0; t<2; t++){
            const bf16* base = aB[t];
            #pragma unroll
            for (int j = tid; j < BM*4; j += 256){
                int row = j >> 2, ch = j & 3;
                cp16(stg + t*TA + row*80 + ch*16, base + (long)row*p.lda + ch*8);
            }
        }
        const bf16* bB[2] = { p.Bh + boff + bT[tap] + k0, p.Bl + boff + bT[tap] + k0 };
        #pragma unroll
        for (int t=0; t<2; t++){
            const bf16* base = bB[t];
            #pragma unroll
            for (int j = tid; j < 512; j += 256){
                int row = j >> 2, ch = j & 3;
                cp16(stg + 2*TA + t*TB + row*80 + ch*16, base + (long)row*p.ldb + ch*8);
            }
        }
    };

    loadChunk(0); cp_commit();
    if (nch > 1){ loadChunk(1); cp_commit(); }

    for (int c=0; c<nch; c++){
        if (c+2 < nch){ loadChunk(c+2); cp_commit(); cp_wait2(); }
        else if (c+1 < nch){ cp_wait1(); }
        else { cp_wait0(); }
        __syncthreads();

        uint32_t stg = smb + (c % 3)*STG;
        uint32_t aH = stg, aL = stg + TA, bH = stg + 2*TA, bL = stg + 2*TA + TB;

        int lr = lane & 15, lcs = lane >> 4;
        int gb = lane >> 3, bnr = lane & 7;
        int rowA = wm*(MT*16) + lr;
        int rowB = wn*32 + ((gb >> 1) << 3) + bnr;

        #pragma unroll
        for (int ks=0; ks<2; ks++){
            uint32_t ahf[MT][4], alf[MT][4], bhf[4][2], blf[4][2];
            uint32_t aoffb = (uint32_t)((rowA*5 + ks*2 + lcs) * 16);
            #pragma unroll
            for (int mt=0; mt<MT; mt++){
                ldsm_x4(ahf[mt], aH + aoffb + mt*1280);
                ldsm_x4(alf[mt], aL + aoffb + mt*1280);
            }
            uint32_t boffb = (uint32_t)((rowB*5 + ks*2 + (gb & 1)) * 16);
            uint32_t t4[4];
            #pragma unroll
            for (int np=0; np<2; np++){
                ldsm_x4(t4, bH + boffb + np*1280);
                bhf[np*2][0]=t4[0]; bhf[np*2][1]=t4[1]; bhf[np*2+1][0]=t4[2]; bhf[np*2+1][1]=t4[3];
                ldsm_x4(t4, bL + boffb + np*1280);
                blf[np*2][0]=t4[0]; blf[np*2][1]=t4[1]; blf[np*2+1][0]=t4[2]; blf[np*2+1][1]=t4[3];
            }
            #pragma unroll
            for (int mt=0; mt<MT; mt++)
                #pragma unroll
                for (int nt=0; nt<4; nt++){
                    mma16816(acc[mt][nt], ahf[mt], bhf[nt]);
                    mma16816(acc[mt][nt], ahf[mt], blf[nt]);
                    mma16816(acc[mt][nt], alf[mt], bhf[nt]);
                }
        }
        __syncthreads();
    }

    float* eps = (float*)sm;
    #pragma unroll
    for (int mt=0; mt<MT; mt++){
        int r0 = wm*(MT*16) + mt*16 + (lane >> 2);
        #pragma unroll
        for (int nt=0; nt<4; nt++){
            int c0 = wn*32 + nt*8 + (lane & 3)*2;
            eps[r0*132 + c0]       = acc[mt][nt][0];
            eps[r0*132 + c0 + 1]   = acc[mt][nt][1];
            eps[(r0+8)*132 + c0]   = acc[mt][nt][2];
            eps[(r0+8)*132 + c0+1] = acc[mt][nt][3];
        }
    }
    __syncthreads();

    const float* bias = p.bias ? (p.bias + (long)blockIdx.z*p.biasZ) : (const float*)0;
    long czo = (long)blockIdx.z * p.cZ;
    long ozo = (long)blockIdx.z * p.oZ;
    for (int j = tid; j < BM*128; j += 256){
        int rr = j >> 7, cc = j & 127;
        long m = m0 + rr;
        int n = n0 + cc;
        float val = eps[rr*132 + cc];
        if (bias) val += bias[n];
        if (p.epi & 2){ val = val / (1.f + expf(-val)); }
        if (p.epi & 4){ val += p.add[m*p.ldadd + n]; }
        if (p.Cf) p.Cf[m*p.ldc + czo + n] = val;
        if (n < p.splitNmax){
            bf16 hi, lo; split_bf(val, hi, lo);
            p.Oh[m*p.ldo + ozo + n] = hi;
            p.Ol[m*p.ldo + ozo + n] = lo;
        }
    }
}

// ---------------- gates ----------------
__global__ __launch_bounds__(256) void gates_kernel(const float* __restrict__ proj,
        const float* __restrict__ vb, const float* __restrict__ wif,
        const float* __restrict__ bif, float* __restrict__ gates){
    __shared__ float As[16*128];
    __shared__ float Ws[128*17];
    int m0 = blockIdx.x*16;
    int tid = threadIdx.x;
    int r = tid >> 4, g = tid & 15;
    float acc = 0.f;
    for (int j0=0; j0<6144; j0+=128){
        __syncthreads();
        for (int e=tid; e<2048; e+=256){
            int jj = e & 127, rr = e >> 7;
            int j = j0 + jj;
            int hh = j/768, t = j - hh*768;
            long m = m0 + rr;
            float v = (t < 512) ? proj[m*4096 + hh*512 + t]
                                : vb[m*2048 + hh*256 + (t-512)];
            As[rr*128 + jj] = v;
        }
        for (int e=tid; e<2048; e+=256){
            int jj = e & 127, gg = e >> 7;
            Ws[jj*17 + gg] = wif[(long)gg*6144 + j0 + jj];
        }
        __syncthreads();
        #pragma unroll 8
        for (int j=0;j<128;j++) acc += As[r*128 + j]*Ws[j*17 + g];
    }
    gates[(long)(m0+r)*16 + g] = acc + bif[g];
}

// ---------------- per-(b,h) scans ----------------
__global__ __launch_bounds__(512) void scan_kernel(const float* __restrict__ gates,
        float* __restrict__ ga, float* __restrict__ Ma, float* __restrict__ ea){
    int bh = blockIdx.x, b = bh >> 3, h = bh & 7;
    int t = threadIdx.x;
    __shared__ float sd[512];
    long base = (long)b*Lq;
    float ls[3], fc[3];
    #pragma unroll
    for (int u=0;u<3;u++){
        int l = t*3 + u;
        float f = gates[(base + l)*16 + 8 + h];
        ls[u] = (f >= 0.f) ? -log1pf(expf(-f)) : (f - log1pf(expf(f)));
    }
    float tot = ls[0] + ls[1] + ls[2];
    sd[t] = tot;
    __syncthreads();
    for (int off=1; off<512; off<<=1){
        float add = (t >= off) ? sd[t-off] : 0.f;
        __syncthreads();
        sd[t] += add;
        __syncthreads();
    }
    float excl = (t > 0) ? sd[t-1] : 0.f;
    fc[0] = excl + ls[0]; fc[1] = fc[0] + ls[1]; fc[2] = fc[1] + ls[2];
    __syncthreads();
    float gv[3], pm[3];
    #pragma unroll
    for (int u=0;u<3;u++){
        int l = t*3 + u;
        float ig = gates[(base + l)*16 + h];
        gv[u] = expf(ig) - fc[u];
    }
    pm[0] = gv[0]; pm[1] = fmaxf(pm[0], gv[1]); pm[2] = fmaxf(pm[1], gv[2]);
    sd[t] = pm[2];
    __syncthreads();
    for (int off=1; off<512; off<<=1){
        float add = (t >= off) ? sd[t-off] : -3.4e38f;
        __syncthreads();
        sd[t] = fmaxf(sd[t], add);
        __syncthreads();
    }
    float exm = (t > 0) ? sd[t-1] : -3.4e38f;
    #pragma unroll
    for (int u=0;u<3;u++){
        int l = t*3 + u;
        float Ml = fmaxf(exm, pm[u]);
        ga[(long)bh*Lq + l] = gv[u];
        Ma[(long)bh*Lq + l] = Ml;
        ea[(long)bh*Lq + l] = expf(-fc[u] - Ml);
    }
}

// ---------------- tensor-core mLSTM attention + fused epilogue ----------------
#define QH_OFF 0
#define QL_OFF 33792
#define KB_OFF 67584
#define VB_OFF 104448
#define E_OFF  141312
#define ATT_SMEM 141568

__global__ __launch_bounds__(128, 1) void attn2(
    const bf16* __restrict__ pjh, const bf16* __restrict__ pjl,
    const bf16* __restrict__ vbh, const bf16* __restrict__ vbl,
    const float* __restrict__ qk, const float* __restrict__ y,
    const float* __restrict__ ga, const float* __restrict__ Ma,
    const float* __restrict__ ea, const float* __restrict__ skip,
    const float* __restrict__ hnw,
    bf16* __restrict__ xmh, bf16* __restrict__ xml)
{
    extern __shared__ char sm[];
    const uint32_t smb = smem_u32(sm);
    float* Esm = (float*)(sm + E_OFF);

    int tid = threadIdx.x, w = tid >> 5, lane = tid & 31;
    int bh = blockIdx.y, b = bh >> 3, h = bh & 7;
    int qt = (int)gridDim.x - 1 - (int)blockIdx.x;
    long mbase = (long)b*Lq;
    int o0 = qt*64;

    int rowg = w*16 + (lane >> 2);
    float F0  = expf(-Ma[(long)bh*Lq + o0 + rowg])     * 0.0625f;
    float F8  = expf(-Ma[(long)bh*Lq + o0 + rowg + 8]) * 0.0625f;
    float en0 = ea[(long)bh*Lq + o0 + rowg];
    float en8 = ea[(long)bh*Lq + o0 + rowg + 8];

    for (int j = tid; j < 4096; j += 128){
        int t = j >> 11, rem = j & 2047;
        int row = rem >> 5, c = rem & 31;
        const bf16* src = (t ? pjl : pjh) + (mbase + o0 + row)*4096 + h*512 + c*8;
        cp16(smb + (t ? QL_OFF : QH_OFF) + row*528 + c*16, src);
    }
    cp_commit();

    int total = (qt + 1)*8;
    auto issueItem = [&](int idx){
        int it = idx >> 3, sub = idx & 7;
        long i0 = (long)it*64;
        uint32_t buf; const bf16 *sh, *sl; long ldg, goff;
        if (sub < 4){ buf = smb + KB_OFF + (sub & 1)*18432; sh = pjh; sl = pjl; ldg = 4096; goff = h*512 + 256 + sub*64; }
        else        { buf = smb + VB_OFF + (sub & 1)*18432; sh = vbh; sl = vbl; ldg = 2048; goff = h*256 + (sub - 4)*64; }
        for (int j = tid; j < 1024; j += 128){
            int t = j >> 9, rem = j & 511;
            int row = rem >> 3, c8 = rem & 7;
            const bf16* src = (t ? sl : sh) + (mbase + i0 + row)*ldg + goff + c8*8;
            cp16(buf + t*9216 + row*144 + c8*16, src);
        }
    };
    issueItem(0); cp_commit();
    if (total > 1) issueItem(1);
    cp_commit();

    float accH[32][4];
    #pragma unroll
    for (int g=0; g<32; g++){ accH[g][0]=0.f; accH[g][1]=0.f; accH[g][2]=0.f; accH[g][3]=0.f; }
    float sacc[8][4];
    uint32_t pkh[8][2], pkl[8][2];
    float rs0 = 0.f, rs1 = 0.f;

    uint32_t qrow = (uint32_t)((w*16 + (lane & 15))*528 + (lane >> 4)*16);
    int gb = lane >> 3;
    uint32_t krow = (uint32_t)(((((gb >> 1) << 3) + (lane & 7)))*144 + (gb & 1)*16);
    uint32_t vrow = (uint32_t)((lane & 15)*144 + (lane >> 4)*16);

    for (int idx = 0; idx < total; idx++){
        int it = idx >> 3, sub = idx & 7;
        cp_wait1();
        __syncthreads();
        if (sub < 4){
            if (sub == 0){
                if (tid < 64) Esm[tid] = expf(ga[(long)bh*Lq + (long)it*64 + tid]);
                #pragma unroll
                for (int g=0; g<8; g++){ sacc[g][0]=0.f; sacc[g][1]=0.f; sacc[g][2]=0.f; sacc[g][3]=0.f; }
            }
            uint32_t kb = smb + KB_OFF + (sub & 1)*18432;
            #pragma unroll
            for (int ks=0; ks<4; ks++){
                uint32_t qa = qrow + sub*128 + ks*32;
                uint32_t qh4[4], ql4[4];
                ldsm_x4(qh4, smb + QH_OFF + qa);
                ldsm_x4(ql4, smb + QL_OFF + qa);
                #pragma unroll
                for (int kt=0; kt<4; kt++){
                    uint32_t ka = kb + krow + kt*(16*144) + ks*32;
                    uint32_t bh4[4], bl4[4];
                    ldsm_x4(bh4, ka);
                    ldsm_x4(bl4, ka + 9216);
                    mma16816(sacc[kt*2],   qh4, bh4);
                    mma16816(sacc[kt*2],   qh4, bl4);
                    mma16816(sacc[kt*2],   ql4, bh4);
                    mma16816(sacc[kt*2+1], qh4, bh4 + 2);
                    mma16816(sacc[kt*2+1], qh4, bl4 + 2);
                    mma16816(sacc[kt*2+1], ql4, bh4 + 2);
                }
            }
            if (sub == 3){
                bool diag = (it == qt);
                #pragma unroll
                for (int nt=0; nt<8; nt++){
                    int cb = nt*8 + (lane & 3)*2;
                    float e0 = Esm[cb], e1 = Esm[cb+1];
                    float w00 = e0*F0, w01 = e1*F0, w10 = e0*F8, w11 = e1*F8;
                    if (diag){
                        if (cb     > rowg)     w00 = 0.f;
                        if (cb + 1 > rowg)     w01 = 0.f;
                        if (cb     > rowg + 8) w10 = 0.f;
                        if (cb + 1 > rowg + 8) w11 = 0.f;
                    }
                    float c0 = sacc[nt][0]*w00, c1 = sacc[nt][1]*w01;
                    float c2 = sacc[nt][2]*w10, c3 = sacc[nt][3]*w11;
                    rs0 += c0 + c1; rs1 += c2 + c3;
                    bf16 h0,l0,h1,l1;
                    split_bf(c0, h0, l0); split_bf(c1, h1, l1);
                    pkh[nt][0] = pack2(h0, h1); pkl[nt][0] = pack2(l0, l1);
                    split_bf(c2, h0, l0); split_bf(c3, h1, l1);
                    pkh[nt][1] = pack2(h0, h1); pkl[nt][1] = pack2(l0, l1);
                }
            }
        } else {
            int vc = sub - 4;
            uint32_t vbb = smb + VB_OFF + (sub & 1)*18432;
            #pragma unroll
            for (int kk=0; kk<4; kk++){
                uint32_t aH[4] = { pkh[2*kk][0], pkh[2*kk][1], pkh[2*kk+1][0], pkh[2*kk+1][1] };
                uint32_t aL[4] = { pkl[2*kk][0], pkl[2*kk][1], pkl[2*kk+1][0], pkl[2*kk+1][1] };
                #pragma unroll
                for (int np=0; np<4; np++){
                    uint32_t va = vbb + vrow + kk*(16*144) + np*32;
                    uint32_t tH[4], tL[4];
                    ldsm_x4t(tH, va);
                    ldsm_x4t(tL, va + 9216);
                    int g0 = vc*8 + 2*np;
                    mma16816(accH[g0],   aH, tH);
                    mma16816(accH[g0],   aH, tL);
                    mma16816(accH[g0],   aL, tH);
                    mma16816(accH[g0+1], aH, tH + 2);
                    mma16816(accH[g0+1], aH, tL + 2);
                    mma16816(accH[g0+1], aL, tH + 2);
                }
            }
        }
        __syncthreads();
        if (idx + 2 < total) issueItem(idx + 2);
        cp_commit();
    }

    rs0 += __shfl_xor_sync(0xffffffffu, rs0, 1);
    rs0 += __shfl_xor_sync(0xffffffffu, rs0, 2);
    rs1 += __shfl_xor_sync(0xffffffffu, rs1, 1);
    rs1 += __shfl_xor_sync(0xffffffffu, rs1, 2);
    float inv0 = 1.f / fmaxf(fabsf(rs0), en0);
    float inv1 = 1.f / fmaxf(fabsf(rs1), en8);

    float s0=0.f, q0=0.f, s1=0.f, q1=0.f;
    #pragma unroll
    for (int g=0; g<32; g++){
        float v0 = accH[g][0]*inv0, v1 = accH[g][1]*inv0;
        float v2 = accH[g][2]*inv1, v3 = accH[g][3]*inv1;
        accH[g][0]=v0; accH[g][1]=v1; accH[g][2]=v2; accH[g][3]=v3;
        s0 += v0 + v1; q0 += v0*v0 + v1*v1;
        s1 += v2 + v3; q1 += v2*v2 + v3*v3;
    }
    s0 += __shfl_xor_sync(0xffffffffu, s0, 1); s0 += __shfl_xor_sync(0xffffffffu, s0, 2);
    q0 += __shfl_xor_sync(0xffffffffu, q0, 1); q0 += __shfl_xor_sync(0xffffffffu, q0, 2);
    s1 += __shfl_xor_sync(0xffffffffu, s1, 1); s1 += __shfl_xor_sync(0xffffffffu, s1, 2);
    q1 += __shfl_xor_sync(0xffffffffu, q1, 1); q1 += __shfl_xor_sync(0xffffffffu, q1, 2);
    float mu0 = s0*(1.f/256.f), var0 = q0*(1.f/256.f) - mu0*mu0, rst0 = rsqrtf(var0 + 1e-5f);
    float mu1 = s1*(1.f/256.f), var1 = q1*(1.f/256.f) - mu1*mu1, rst1 = rsqrtf(var1 + 1e-5f);

    long mr0 = mbase + o0 + rowg;
    long mr8 = mr0 + 8;
    #pragma unroll
    for (int g=0; g<32; g++){
        int d0 = g*8 + (lane & 3)*2;
        int col = h*256 + d0;
        float2 hw = *(const float2*)(hnw + d0);
        float2 sk = *(const float2*)(skip + col);
        {
            float2 q2 = *(const float2*)(qk + mr0*2048 + col);
            float2 x2 = *(const float2*)(y + mr0*4096 + 2048 + col);
            float hv0 = (accH[g][0] - mu0)*rst0*hw.x;
            float hv1 = (accH[g][1] - mu0)*rst0*hw.y;
            float a0 = hv0 + sk.x*q2.x, a1 = hv1 + sk.y*q2.y;
            float r0 = a0 * (x2.x / (1.f + expf(-x2.x)));
            float r1 = a1 * (x2.y / (1.f + expf(-x2.y)));
            bf16 hh0,ll0,hh1,ll1; split_bf(r0,hh0,ll0); split_bf(r1,hh1,ll1);
            *(uint32_t*)(xmh + mr0*2048 + col) = pack2(hh0, hh1);
            *(uint32_t*)(xml + mr0*2048 + col) = pack2(ll0, ll1);
        }
        {
            float2 q2 = *(const float2*)(qk + mr8*2048 + col);
            float2 x2 = *(const float2*)(y + mr8*4096 + 2048 + col);
            float hv0 = (accH[g][2] - mu1)*rst1*hw.x;
            float hv1 = (accH[g][3] - mu1)*rst1*hw.y;
            float a0 = hv0 + sk.x*q2.x, a1 = hv1 + sk.y*q2.y;
            float r0 = a0 * (x2.x / (1.f + expf(-x2.x)));
            float r1 = a1 * (x2.y / (1.f + expf(-x2.y)));
            bf16 hh0,ll0,hh1,ll1; split_bf(r0,hh0,ll0); split_bf(r1,hh1,ll1);
            *(uint32_t*)(xmh + mr8*2048 + col) = pack2(hh0, hh1);
            *(uint32_t*)(xml + mr8*2048 + col) = pack2(ll0, ll1);
        }
    }
}

// ---------------- host ----------------
extern "C" void kernel_launch(void* const* d_in, const int* in_sizes, int n_in,
                              void* d_out, int out_size){
    const float* x      = (const float*)d_in[0];
    const float* ln_w   = (const float*)d_in[1];
    const float* ln_b   = (const float*)d_in[2];
    const float* w1     = (const float*)d_in[3];
    const float* b1     = (const float*)d_in[4];
    const float* conv_w = (const float*)d_in[5];
    const float* conv_b = (const float*)d_in[6];
    const float* skip   = (const float*)d_in[7];
    const float* wqk    = (const float*)d_in[8];
    const float* bqk    = (const float*)d_in[9];
    const float* wv     = (const float*)d_in[10];
    const float* bv     = (const float*)d_in[11];
    const float* wif    = (const float*)d_in[12];
    const float* bif    = (const float*)d_in[13];
    const float* hn_w   = (const float*)d_in[14];
    const float* w2     = (const float*)d_in[15];
    const float* b2     = (const float*)d_in[16];
    float* out = (float*)d_out;

    bf16 *xlnh,*xlnl,*x1h,*x1l,*qkh,*qkl,*xmh,*xml,*pjh,*pjl,*vbh,*vbl;
    bf16 *w1h,*w1l,*cwth,*cwtl,*wqkTh,*wqkTl,*wvTh,*wvTl,*w2h,*w2l;
    float *y,*qkb,*proj,*vbuf,*gates,*gA,*MA,*eA;
    cudaGetSymbolAddress((void**)&xlnh, d_xlnh);  cudaGetSymbolAddress((void**)&xlnl, d_xlnl);
    cudaGetSymbolAddress((void**)&y,    d_y);
    cudaGetSymbolAddress((void**)&x1h,  d_x1h);   cudaGetSymbolAddress((void**)&x1l,  d_x1l);
    cudaGetSymbolAddress((void**)&qkb,  d_qk);
    cudaGetSymbolAddress((void**)&qkh,  d_qkh);   cudaGetSymbolAddress((void**)&qkl,  d_qkl);
    cudaGetSymbolAddress((void**)&proj, d_proj);
    cudaGetSymbolAddress((void**)&pjh,  d_pjh);   cudaGetSymbolAddress((void**)&pjl,  d_pjl);
    cudaGetSymbolAddress((void**)&vbuf, d_v);
    cudaGetSymbolAddress((void**)&vbh,  d_vbh);   cudaGetSymbolAddress((void**)&vbl,  d_vbl);
    cudaGetSymbolAddress((void**)&xmh,  d_xmh);   cudaGetSymbolAddress((void**)&xml,  d_xml);
    cudaGetSymbolAddress((void**)&gates,d_gates);
    cudaGetSymbolAddress((void**)&gA,   d_g);
    cudaGetSymbolAddress((void**)&MA,   d_M);
    cudaGetSymbolAddress((void**)&eA,   d_enm);
    cudaGetSymbolAddress((void**)&w1h,  d_w1h);   cudaGetSymbolAddress((void**)&w1l,  d_w1l);
    cudaGetSymbolAddress((void**)&cwth, d_cwth);  cudaGetSymbolAddress((void**)&cwtl, d_cwtl);
    cudaGetSymbolAddress((void**)&wqkTh,d_wqkTh); cudaGetSymbolAddress((void**)&wqkTl,d_wqkTl);
    cudaGetSymbolAddress((void**)&wvTh, d_wvTh);  cudaGetSymbolAddress((void**)&wvTl, d_wvTl);
    cudaGetSymbolAddress((void**)&w2h,  d_w2h);   cudaGetSymbolAddress((void**)&w2l,  d_w2l);

    cudaFuncSetAttribute(hgemm<4>, cudaFuncAttributeMaxDynamicSharedMemorySize, 122880);
    cudaFuncSetAttribute(hgemm<2>, cudaFuncAttributeMaxDynamicSharedMemorySize, 92160);
    cudaFuncSetAttribute(attn2, cudaFuncAttributeMaxDynamicSharedMemorySize, ATT_SMEM);

    split_plain<<<(4096*1024 + 255)/256, 256>>>(w1, w1h, w1l, (long)4096*1024);
    split_plain<<<(1024*2048 + 255)/256, 256>>>(w2, w2h, w2l, (long)1024*2048);
    prep_cwt<<<(int)(((long)4*Cq*Cq + 255)/256), 256>>>(conv_w, cwth, cwtl);
    prep_wqkv<<<(Hq*512*256 + Hq*256*256 + 255)/256, 256>>>(wqk, wv, wqkTh, wqkTl, wvTh, wvTl);

    ln_kernel<<<Mq, 256>>>(x, ln_w, ln_b, xlnh, xlnl);

    // y = LN(x) @ w1^T + b1 : f32 y + bf16 split of x1 (cols < 2048)
    {
        G5P p = {};
        p.Ah = xlnh; p.Al = xlnl; p.Bh = w1h; p.Bl = w1l;
        p.Cf = y; p.Oh = x1h; p.Ol = x1l; p.bias = b1;
        p.K = 1024; p.lda = 1024; p.ldb = 1024; p.ldc = 4096; p.ldo = 2048;
        p.epi = 1; p.ntaps = 1; p.splitNmax = 2048;
        hgemm<4><<<dim3(32, 24, 1), 256, 122880>>>(p);
    }

    // qk = silu(conv(x1)) — single launch, batch-dependent taps (conv over batch axis)
    {
        G5P p = {};
        p.Ah = x1h; p.Al = x1l; p.Bh = cwth; p.Bl = cwtl;
        p.Cf = qkb; p.Oh = qkh; p.Ol = qkl; p.bias = conv_b;
        p.K = Cq; p.lda = Cq; p.ldb = Cq; p.ldc = Cq; p.ldo = Cq;
        p.epi = 1|2|8; p.splitNmax = Cq;
        // batch 0: qk[0] = x1[0] @ W_k3
        p.ntaps  = 1; p.aTap[0]  = 0;              p.bTap[0]  = (long)3*Cq*Cq;
        // batch 1: qk[1] = x1[0] @ W_k2 + x1[1] @ W_k3
        p.ntaps2 = 2; p.aTap2[0] = 0;              p.bTap2[0] = (long)2*Cq*Cq;
                      p.aTap2[1] = (long)Lq*Cq;    p.bTap2[1] = (long)3*Cq*Cq;
        hgemm<4><<<dim3(16, 24, 1), 256, 122880>>>(p);
    }

    // per-head proj = qk_h @ wqk_h + bqk  (f32 for gates + bf16 hi/lo for attention)
    {
        G5P p = {};
        p.Ah = qkh; p.Al = qkl; p.Bh = wqkTh; p.Bl = wqkTl;
        p.Cf = proj; p.Oh = pjh; p.Ol = pjl; p.bias = bqk;
        p.K = 256; p.lda = 2048; p.ldb = 256; p.ldc = 4096; p.ldo = 4096;
        p.aZ = 256; p.bZ = (long)512*256; p.cZ = 512; p.biasZ = 512; p.oZ = 512;
        p.epi = 1; p.ntaps = 1; p.splitNmax = 512;
        hgemm<4><<<dim3(4, 24, Hq), 256, 122880>>>(p);
    }
    // per-head v = x1_h @ wv_h + bv  (f32 + bf16 hi/lo)
    {
        G5P p = {};
        p.Ah = x1h; p.Al = x1l; p.Bh = wvTh; p.Bl = wvTl;
        p.Cf = vbuf; p.Oh = vbh; p.Ol = vbl; p.bias = bv;
        p.K = 256; p.lda = 2048; p.ldb = 256; p.ldc = 2048; p.ldo = 2048;
        p.aZ = 256; p.bZ = (long)256*256; p.cZ = 256; p.biasZ = 256; p.oZ = 256;
        p.epi = 1; p.ntaps = 1; p.splitNmax = 256;
        hgemm<4><<<dim3(2, 24, Hq), 256, 122880>>>(p);
    }

    gates_kernel<<<Mq/16, 256>>>(proj, vbuf, wif, bif, gates);
    scan_kernel<<<Bq*Hq, 512>>>(gates, gA, MA, eA);

    attn2<<<dim3(24, 16), 128, ATT_SMEM>>>(pjh, pjl, vbh, vbl, qkb, y,
                                           gA, MA, eA, skip, hn_w, xmh, xml);

    // out = xm @ w2^T + b2 + x  (BM=64 tiles → 384 blocks, better wave fill)
    {
        G5P p = {};
        p.Ah = xmh; p.Al = xml; p.Bh = w2h; p.Bl = w2l;
        p.Cf = out; p.bias = b2; p.add = x;
        p.K = Cq; p.lda = 2048; p.ldb = 2048; p.ldc = 1024; p.ldadd = 1024;
        p.epi = 1|4; p.ntaps = 1; p.splitNmax = 0;
        hgemm<2><<<dim3(8, 48, 1), 256, 92160>>>(p);
    }
}

// round 7
// speedup vs baseline: 3.3114x; 1.2868x over previous
#include <cuda_runtime.h>
#include <cuda_fp16.h>
#include <math.h>
#include <stdint.h>

#define Bq 2
#define Lq 1536
#define Dq 1024
#define Hq 8
#define Cq 2048
#define DPHq 256
#define Mq (Bq*Lq)   /* 3072 */

typedef __half fp16;

// ---------------- scratch (static device globals; no allocation) ----------------
__device__ __align__(128) fp16  d_xlnh[(size_t)Mq*Dq],  d_xlnl[(size_t)Mq*Dq];
__device__ __align__(128) float d_y[(size_t)Mq*4096];
__device__ __align__(128) fp16  d_x1h[(size_t)Mq*Cq],  d_x1l[(size_t)Mq*Cq];
__device__ __align__(128) float d_qk[(size_t)Mq*Cq];
__device__ __align__(128) fp16  d_qkh[(size_t)Mq*Cq],  d_qkl[(size_t)Mq*Cq];
__device__ __align__(128) float d_proj[(size_t)Mq*4096];
__device__ __align__(128) fp16  d_pjh[(size_t)Mq*4096], d_pjl[(size_t)Mq*4096];
__device__ __align__(128) float d_v[(size_t)Mq*Cq];
__device__ __align__(128) fp16  d_vbh[(size_t)Mq*Cq],  d_vbl[(size_t)Mq*Cq];
__device__ __align__(128) fp16  d_xmh[(size_t)Mq*Cq],  d_xml[(size_t)Mq*Cq];
__device__ float d_gates[(size_t)Mq*16];
__device__ float d_g[16*Lq];
__device__ float d_M[16*Lq];
__device__ float d_enm[16*Lq];
__device__ __align__(128) fp16  d_w1f[4096*1024];
__device__ __align__(128) fp16  d_cwtf[(size_t)4*Cq*Cq];
__device__ __align__(128) fp16  d_wqkTf[Hq*512*256];
__device__ __align__(128) fp16  d_wvTf[Hq*256*256];
__device__ __align__(128) fp16  d_w2f[1024*2048];

// ---------------- helpers ----------------
__device__ __forceinline__ uint32_t smem_u32(const void* p){
    return (uint32_t)__cvta_generic_to_shared(p);
}
__device__ __forceinline__ void cp16(uint32_t dst, const void* src){
    asm volatile("cp.async.cg.shared.global [%0], [%1], 16;" :: "r"(dst), "l"(src));
}
__device__ __forceinline__ void cp_commit(){ asm volatile("cp.async.commit_group;" ::: "memory"); }
__device__ __forceinline__ void cp_wait0(){ asm volatile("cp.async.wait_group 0;" ::: "memory"); }
__device__ __forceinline__ void cp_wait1(){ asm volatile("cp.async.wait_group 1;" ::: "memory"); }
__device__ __forceinline__ void cp_wait2(){ asm volatile("cp.async.wait_group 2;" ::: "memory"); }

__device__ __forceinline__ void ldsm_x4(uint32_t* r, uint32_t addr){
    asm volatile("ldmatrix.sync.aligned.m8n8.x4.shared.b16 {%0,%1,%2,%3}, [%4];"
                 : "=r"(r[0]), "=r"(r[1]), "=r"(r[2]), "=r"(r[3]) : "r"(addr));
}
__device__ __forceinline__ void ldsm_x4t(uint32_t* r, uint32_t addr){
    asm volatile("ldmatrix.sync.aligned.m8n8.x4.trans.shared.b16 {%0,%1,%2,%3}, [%4];"
                 : "=r"(r[0]), "=r"(r[1]), "=r"(r[2]), "=r"(r[3]) : "r"(addr));
}
__device__ __forceinline__ void mma16816(float* d, const uint32_t* a, const uint32_t* b){
    asm volatile(
        "mma.sync.aligned.m16n8k16.row.col.f32.f16.f16.f32 "
        "{%0,%1,%2,%3}, {%4,%5,%6,%7}, {%8,%9}, {%0,%1,%2,%3};"
        : "+f"(d[0]), "+f"(d[1]), "+f"(d[2]), "+f"(d[3])
        : "r"(a[0]), "r"(a[1]), "r"(a[2]), "r"(a[3]), "r"(b[0]), "r"(b[1]));
}
__device__ __forceinline__ void split_h(float v, fp16& hi, fp16& lo){
    hi = __float2half_rn(v);
    lo = __float2half_rn(v - __half2float(hi));
}
__device__ __forceinline__ uint32_t pack2(fp16 a, fp16 b){
    uint16_t ua = *(uint16_t*)&a, ub = *(uint16_t*)&b;
    return (uint32_t)ua | ((uint32_t)ub << 16);
}

// ---------------- prep kernels (single fp16 weight quantization) ----------------
__global__ void quant_plain(const float* __restrict__ w, fp16* __restrict__ f, long n){
    long i = (long)blockIdx.x*256 + threadIdx.x;
    if (i >= n) return;
    f[i] = __float2half_rn(w[i]);
}
__global__ void prep_cwt(const float* __restrict__ cw, fp16* __restrict__ f){
    long idx = (long)blockIdx.x*256 + threadIdx.x;
    if (idx >= (long)4*Cq*Cq) return;
    int k  = (int)(idx >> 22);
    long rem = idx & ((1L<<22)-1);
    int co = (int)(rem >> 11), ci = (int)(rem & 2047);
    f[idx] = __float2half_rn(cw[(((long)co<<11) + ci)*4 + k]);
}
__global__ void prep_wqkv(const float* __restrict__ wqk, const float* __restrict__ wv,
                          fp16* __restrict__ qf, fp16* __restrict__ vf){
    int idx = blockIdx.x*256 + threadIdx.x;
    if (idx < Hq*512*256){
        int hh = idx/(512*256); int r = idx%(512*256); int o = r/256; int i = r%256;
        qf[idx] = __float2half_rn(wqk[hh*131072 + i*512 + o]);
    } else {
        int j = idx - Hq*512*256;
        if (j < Hq*256*256){
            int hh = j/65536; int r = j%65536; int o = r/256; int i = r%256;
            vf[j] = __float2half_rn(wv[hh*65536 + i*256 + o]);
        }
    }
}

// ---------------- LayerNorm on x -> fp16 hi/lo ----------------
__global__ __launch_bounds__(256) void ln_kernel(const float* __restrict__ x,
        const float* __restrict__ w, const float* __restrict__ bb,
        fp16* __restrict__ oh, fp16* __restrict__ ol){
    int m = blockIdx.x, t = threadIdx.x;
    __shared__ float s1[256], s2[256];
    float v[4]; float s = 0.f, q = 0.f;
    #pragma unroll
    for (int u=0;u<4;u++){ v[u] = x[(long)m*Dq + t + u*256]; s += v[u]; q += v[u]*v[u]; }
    s1[t] = s; s2[t] = q; __syncthreads();
    for (int off=128; off; off>>=1){
        if (t < off){ s1[t] += s1[t+off]; s2[t] += s2[t+off]; }
        __syncthreads();
    }
    float mu = s1[0]*(1.f/1024.f);
    float var = s2[0]*(1.f/1024.f) - mu*mu;
    float rs = rsqrtf(var + 1e-5f);
    #pragma unroll
    for (int u=0;u<4;u++){
        int c = t + u*256;
        float val = (v[u]-mu)*rs*w[c] + bb[c];
        fp16 hi, lo; split_h(val, hi, lo);
        oh[(long)m*Dq + c] = hi; ol[(long)m*Dq + c] = lo;
    }
}

// ---------------- fp16x2 mma.sync GEMM: C = A @ B^T (NT, K-major) ----------------
// A split hi/lo fp16 (2 products), B single fp16.
// epi bits: 1=bias, 2=silu, 4=residual add, 8=conv mode (batch-dependent taps)
struct G5P {
    const fp16 *Ah, *Al, *Bf;
    float* Cf;
    fp16 *Oh, *Ol;
    const float* bias; const float* add;
    int K, lda, ldb, ldc, ldo, ldadd, epi, ntaps, ntaps2, splitNmax;
    long aZ, bZ, cZ, biasZ, oZ;
    long aTap[2], bTap[2];
    long aTap2[2], bTap2[2];
};

template<int MT>
__global__ __launch_bounds__(256, 1) void hgemm(G5P p){
    constexpr int BM = MT*32;
    constexpr int TA = BM*80;
    constexpr int TB = 10240;
    constexpr int STG = 2*TA + TB;
    extern __shared__ char sm[];
    int tid = threadIdx.x;
    int warp = tid >> 5, lane = tid & 31;
    int wm = warp >> 2, wn = warp & 3;

    long m0 = (long)blockIdx.y*BM;
    int  n0 = blockIdx.x*128;

    long arow; int ntaps; long aT[2], bT[2];
    if (p.epi & 8){
        int batch = (int)(m0 / Lq);
        arow = m0 - (long)batch*Lq;
        if (batch == 0){ ntaps = p.ntaps;  aT[0]=p.aTap[0];  bT[0]=p.bTap[0];  aT[1]=p.aTap[1];  bT[1]=p.bTap[1]; }
        else           { ntaps = p.ntaps2; aT[0]=p.aTap2[0]; bT[0]=p.bTap2[0]; aT[1]=p.aTap2[1]; bT[1]=p.bTap2[1]; }
    } else {
        arow = m0; ntaps = p.ntaps;
        aT[0]=p.aTap[0]; bT[0]=p.bTap[0]; aT[1]=p.aTap[1]; bT[1]=p.bTap[1];
    }

    long aoff = (long)blockIdx.z*p.aZ + arow*p.lda;
    long boff = (long)blockIdx.z*p.bZ + (long)n0*p.ldb;
    int cpt = p.K >> 5;
    int nch = ntaps * cpt;

    uint32_t smb = smem_u32(sm);
    float acc[MT][4][4] = {};

    auto loadChunk = [&](int c){
        int tap = c / cpt;
        int k0  = (c - tap*cpt) << 5;
        uint32_t stg = smb + (c % 3)*STG;
        const fp16* aB[2] = { p.Ah + aoff + aT[tap] + k0, p.Al + aoff + aT[tap] + k0 };
        #pragma unroll
        for (int t=0; t<2; t++){
            const fp16* base = aB[t];
            #pragma unroll
            for (int j = tid; j < BM*4; j += 256){
                int row = j >> 2, ch = j & 3;
                cp16(stg + t*TA + row*80 + ch*16, base + (long)row*p.lda + ch*8);
            }
        }
        const fp16* base = p.Bf + boff + bT[tap] + k0;
        #pragma unroll
        for (int j = tid; j < 512; j += 256){
            int row = j >> 2, ch = j & 3;
            cp16(stg + 2*TA + row*80 + ch*16, base + (long)row*p.ldb + ch*8);
        }
    };

    loadChunk(0); cp_commit();
    if (nch > 1){ loadChunk(1); cp_commit(); }

    for (int c=0; c<nch; c++){
        if (c+2 < nch){ loadChunk(c+2); cp_commit(); cp_wait2(); }
        else if (c+1 < nch){ cp_wait1(); }
        else { cp_wait0(); }
        __syncthreads();

        uint32_t stg = smb + (c % 3)*STG;
        uint32_t aH = stg, aL = stg + TA, bB = stg + 2*TA;

        int lr = lane & 15, lcs = lane >> 4;
        int gb = lane >> 3, bnr = lane & 7;
        int rowA = wm*(MT*16) + lr;
        int rowB = wn*32 + ((gb >> 1) << 3) + bnr;

        #pragma unroll
        for (int ks=0; ks<2; ks++){
            uint32_t ahf[MT][4], alf[MT][4], bf[4][2];
            uint32_t aoffb = (uint32_t)((rowA*5 + ks*2 + lcs) * 16);
            #pragma unroll
            for (int mt=0; mt<MT; mt++){
                ldsm_x4(ahf[mt], aH + aoffb + mt*1280);
                ldsm_x4(alf[mt], aL + aoffb + mt*1280);
            }
            uint32_t boffb = (uint32_t)((rowB*5 + ks*2 + (gb & 1)) * 16);
            uint32_t t4[4];
            #pragma unroll
            for (int np=0; np<2; np++){
                ldsm_x4(t4, bB + boffb + np*1280);
                bf[np*2][0]=t4[0]; bf[np*2][1]=t4[1]; bf[np*2+1][0]=t4[2]; bf[np*2+1][1]=t4[3];
            }
            // product-major ordering: hi term across all tiles, then lo term
            #pragma unroll
            for (int mt=0; mt<MT; mt++)
                #pragma unroll
                for (int nt=0; nt<4; nt++)
                    mma16816(acc[mt][nt], ahf[mt], bf[nt]);
            #pragma unroll
            for (int mt=0; mt<MT; mt++)
                #pragma unroll
                for (int nt=0; nt<4; nt++)
                    mma16816(acc[mt][nt], alf[mt], bf[nt]);
        }
        __syncthreads();
    }

    float* eps = (float*)sm;
    #pragma unroll
    for (int mt=0; mt<MT; mt++){
        int r0 = wm*(MT*16) + mt*16 + (lane >> 2);
        #pragma unroll
        for (int nt=0; nt<4; nt++){
            int c0 = wn*32 + nt*8 + (lane & 3)*2;
            eps[r0*132 + c0]       = acc[mt][nt][0];
            eps[r0*132 + c0 + 1]   = acc[mt][nt][1];
            eps[(r0+8)*132 + c0]   = acc[mt][nt][2];
            eps[(r0+8)*132 + c0+1] = acc[mt][nt][3];
        }
    }
    __syncthreads();

    const float* bias = p.bias ? (p.bias + (long)blockIdx.z*p.biasZ) : (const float*)0;
    long czo = (long)blockIdx.z * p.cZ;
    long ozo = (long)blockIdx.z * p.oZ;
    for (int j = tid; j < BM*128; j += 256){
        int rr = j >> 7, cc = j & 127;
        long m = m0 + rr;
        int n = n0 + cc;
        float val = eps[rr*132 + cc];
        if (bias) val += bias[n];
        if (p.epi & 2){ val = val / (1.f + expf(-val)); }
        if (p.epi & 4){ val += p.add[m*p.ldadd + n]; }
        if (p.Cf) p.Cf[m*p.ldc + czo + n] = val;
        if (n < p.splitNmax){
            fp16 hi, lo; split_h(val, hi, lo);
            p.Oh[m*p.ldo + ozo + n] = hi;
            p.Ol[m*p.ldo + ozo + n] = lo;
        }
    }
}

// ---------------- gates ----------------
__global__ __launch_bounds__(256) void gates_kernel(const float* __restrict__ proj,
        const float* __restrict__ vb, const float* __restrict__ wif,
        const float* __restrict__ bif, float* __restrict__ gates){
    __shared__ float As[16*128];
    __shared__ float Ws[128*17];
    int m0 = blockIdx.x*16;
    int tid = threadIdx.x;
    int r = tid >> 4, g = tid & 15;
    float acc = 0.f;
    for (int j0=0; j0<6144; j0+=128){
        __syncthreads();
        for (int e=tid; e<2048; e+=256){
            int jj = e & 127, rr = e >> 7;
            int j = j0 + jj;
            int hh = j/768, t = j - hh*768;
            long m = m0 + rr;
            float v = (t < 512) ? proj[m*4096 + hh*512 + t]
                                : vb[m*2048 + hh*256 + (t-512)];
            As[rr*128 + jj] = v;
        }
        for (int e=tid; e<2048; e+=256){
            int jj = e & 127, gg = e >> 7;
            Ws[jj*17 + gg] = wif[(long)gg*6144 + j0 + jj];
        }
        __syncthreads();
        #pragma unroll 8
        for (int j=0;j<128;j++) acc += As[r*128 + j]*Ws[j*17 + g];
    }
    gates[(long)(m0+r)*16 + g] = acc + bif[g];
}

// ---------------- per-(b,h) scans ----------------
__global__ __launch_bounds__(512) void scan_kernel(const float* __restrict__ gates,
        float* __restrict__ ga, float* __restrict__ Ma, float* __restrict__ ea){
    int bh = blockIdx.x, b = bh >> 3, h = bh & 7;
    int t = threadIdx.x;
    __shared__ float sd[512];
    long base = (long)b*Lq;
    float ls[3], fc[3];
    #pragma unroll
    for (int u=0;u<3;u++){
        int l = t*3 + u;
        float f = gates[(base + l)*16 + 8 + h];
        ls[u] = (f >= 0.f) ? -log1pf(expf(-f)) : (f - log1pf(expf(f)));
    }
    float tot = ls[0] + ls[1] + ls[2];
    sd[t] = tot;
    __syncthreads();
    for (int off=1; off<512; off<<=1){
        float add = (t >= off) ? sd[t-off] : 0.f;
        __syncthreads();
        sd[t] += add;
        __syncthreads();
    }
    float excl = (t > 0) ? sd[t-1] : 0.f;
    fc[0] = excl + ls[0]; fc[1] = fc[0] + ls[1]; fc[2] = fc[1] + ls[2];
    __syncthreads();
    float gv[3], pm[3];
    #pragma unroll
    for (int u=0;u<3;u++){
        int l = t*3 + u;
        float ig = gates[(base + l)*16 + h];
        gv[u] = expf(ig) - fc[u];
    }
    pm[0] = gv[0]; pm[1] = fmaxf(pm[0], gv[1]); pm[2] = fmaxf(pm[1], gv[2]);
    sd[t] = pm[2];
    __syncthreads();
    for (int off=1; off<512; off<<=1){
        float add = (t >= off) ? sd[t-off] : -3.4e38f;
        __syncthreads();
        sd[t] = fmaxf(sd[t], add);
        __syncthreads();
    }
    float exm = (t > 0) ? sd[t-1] : -3.4e38f;
    #pragma unroll
    for (int u=0;u<3;u++){
        int l = t*3 + u;
        float Ml = fmaxf(exm, pm[u]);
        ga[(long)bh*Lq + l] = gv[u];
        Ma[(long)bh*Lq + l] = Ml;
        ea[(long)bh*Lq + l] = expf(-fc[u] - Ml);
    }
}

// ---------------- tensor-core mLSTM attention + fused epilogue ----------------
// smem: Qh 64x528 | Ql | 2 K bufs (9216) | 2 V bufs (9216) | E[64]
#define QH_OFF 0
#define QL_OFF 33792
#define KB_OFF 67584
#define VB_OFF 86016
#define E_OFF  104448
#define ATT_SMEM 104704

__global__ __launch_bounds__(128, 1) void attn2(
    const fp16* __restrict__ pjh, const fp16* __restrict__ pjl,
    const fp16* __restrict__ vbh,
    const float* __restrict__ qk, const float* __restrict__ y,
    const float* __restrict__ ga, const float* __restrict__ Ma,
    const float* __restrict__ ea, const float* __restrict__ skip,
    const float* __restrict__ hnw,
    fp16* __restrict__ xmh, fp16* __restrict__ xml)
{
    extern __shared__ char sm[];
    const uint32_t smb = smem_u32(sm);
    float* Esm = (float*)(sm + E_OFF);

    int tid = threadIdx.x, w = tid >> 5, lane = tid & 31;
    int bh = blockIdx.y, b = bh >> 3, h = bh & 7;
    int qt = (int)gridDim.x - 1 - (int)blockIdx.x;
    long mbase = (long)b*Lq;
    int o0 = qt*64;

    int rowg = w*16 + (lane >> 2);
    float F0  = expf(-Ma[(long)bh*Lq + o0 + rowg])     * 0.0625f;
    float F8  = expf(-Ma[(long)bh*Lq + o0 + rowg + 8]) * 0.0625f;
    float en0 = ea[(long)bh*Lq + o0 + rowg];
    float en8 = ea[(long)bh*Lq + o0 + rowg + 8];

    for (int j = tid; j < 4096; j += 128){
        int t = j >> 11, rem = j & 2047;
        int row = rem >> 5, c = rem & 31;
        const fp16* src = (t ? pjl : pjh) + (mbase + o0 + row)*4096 + h*512 + c*8;
        cp16(smb + (t ? QL_OFF : QH_OFF) + row*528 + c*16, src);
    }
    cp_commit();

    int total = (qt + 1)*8;
    auto issueItem = [&](int idx){
        int it = idx >> 3, sub = idx & 7;
        long i0 = (long)it*64;
        uint32_t buf; const fp16* src0; long ldg, goff;
        if (sub < 4){ buf = smb + KB_OFF + (sub & 1)*9216; src0 = pjh; ldg = 4096; goff = h*512 + 256 + sub*64; }
        else        { buf = smb + VB_OFF + (sub & 1)*9216; src0 = vbh; ldg = 2048; goff = h*256 + (sub - 4)*64; }
        for (int j = tid; j < 512; j += 128){
            int row = j >> 3, c8 = j & 7;
            cp16(buf + row*144 + c8*16, src0 + (mbase + i0 + row)*ldg + goff + c8*8);
        }
    };
    issueItem(0); cp_commit();
    if (total > 1) issueItem(1);
    cp_commit();

    float accH[32][4];
    #pragma unroll
    for (int g=0; g<32; g++){ accH[g][0]=0.f; accH[g][1]=0.f; accH[g][2]=0.f; accH[g][3]=0.f; }
    float sacc[8][4];
    uint32_t pkh[8][2], pkl[8][2];
    float rs0 = 0.f, rs1 = 0.f;

    uint32_t qrow = (uint32_t)((w*16 + (lane & 15))*528 + (lane >> 4)*16);
    int gb = lane >> 3;
    uint32_t krow = (uint32_t)(((((gb >> 1) << 3) + (lane & 7)))*144 + (gb & 1)*16);
    uint32_t vrow = (uint32_t)((lane & 15)*144 + (lane >> 4)*16);

    for (int idx = 0; idx < total; idx++){
        int it = idx >> 3, sub = idx & 7;
        cp_wait1();
        __syncthreads();
        if (sub < 4){
            if (sub == 0){
                if (tid < 64) Esm[tid] = expf(ga[(long)bh*Lq + (long)it*64 + tid]);
                #pragma unroll
                for (int g=0; g<8; g++){ sacc[g][0]=0.f; sacc[g][1]=0.f; sacc[g][2]=0.f; sacc[g][3]=0.f; }
            }
            uint32_t kb = smb + KB_OFF + (sub & 1)*9216;
            #pragma unroll
            for (int ks=0; ks<4; ks++){
                uint32_t qa = qrow + sub*128 + ks*32;
                uint32_t qh4[4], ql4[4];
                ldsm_x4(qh4, smb + QH_OFF + qa);
                ldsm_x4(ql4, smb + QL_OFF + qa);
                #pragma unroll
                for (int kt=0; kt<4; kt++){
                    uint32_t b4[4];
                    ldsm_x4(b4, kb + krow + kt*(16*144) + ks*32);
                    mma16816(sacc[kt*2],   qh4, b4);
                    mma16816(sacc[kt*2],   ql4, b4);
                    mma16816(sacc[kt*2+1], qh4, b4 + 2);
                    mma16816(sacc[kt*2+1], ql4, b4 + 2);
                }
            }
            if (sub == 3){
                bool diag = (it == qt);
                #pragma unroll
                for (int nt=0; nt<8; nt++){
                    int cb = nt*8 + (lane & 3)*2;
                    float e0 = Esm[cb], e1 = Esm[cb+1];
                    float w00 = e0*F0, w01 = e1*F0, w10 = e0*F8, w11 = e1*F8;
                    if (diag){
                        if (cb     > rowg)     w00 = 0.f;
                        if (cb + 1 > rowg)     w01 = 0.f;
                        if (cb     > rowg + 8) w10 = 0.f;
                        if (cb + 1 > rowg + 8) w11 = 0.f;
                    }
                    float c0 = sacc[nt][0]*w00, c1 = sacc[nt][1]*w01;
                    float c2 = sacc[nt][2]*w10, c3 = sacc[nt][3]*w11;
                    rs0 += c0 + c1; rs1 += c2 + c3;
                    fp16 h0,l0,h1,l1;
                    split_h(c0, h0, l0); split_h(c1, h1, l1);
                    pkh[nt][0] = pack2(h0, h1); pkl[nt][0] = pack2(l0, l1);
                    split_h(c2, h0, l0); split_h(c3, h1, l1);
                    pkh[nt][1] = pack2(h0, h1); pkl[nt][1] = pack2(l0, l1);
                }
            }
        } else {
            int vc = sub - 4;
            uint32_t vbb = smb + VB_OFF + (sub & 1)*9216;
            #pragma unroll
            for (int kk=0; kk<4; kk++){
                uint32_t aH[4] = { pkh[2*kk][0], pkh[2*kk][1], pkh[2*kk+1][0], pkh[2*kk+1][1] };
                uint32_t aL[4] = { pkl[2*kk][0], pkl[2*kk][1], pkl[2*kk+1][0], pkl[2*kk+1][1] };
                #pragma unroll
                for (int np=0; np<4; np++){
                    uint32_t tH[4];
                    ldsm_x4t(tH, vbb + vrow + kk*(16*144) + np*32);
                    int g0 = vc*8 + 2*np;
                    mma16816(accH[g0],   aH, tH);
                    mma16816(accH[g0],   aL, tH);
                    mma16816(accH[g0+1], aH, tH + 2);
                    mma16816(accH[g0+1], aL, tH + 2);
                }
            }
        }
        __syncthreads();
        if (idx + 2 < total) issueItem(idx + 2);
        cp_commit();
    }

    rs0 += __shfl_xor_sync(0xffffffffu, rs0, 1);
    rs0 += __shfl_xor_sync(0xffffffffu, rs0, 2);
    rs1 += __shfl_xor_sync(0xffffffffu, rs1, 1);
    rs1 += __shfl_xor_sync(0xffffffffu, rs1, 2);
    float inv0 = 1.f / fmaxf(fabsf(rs0), en0);
    float inv1 = 1.f / fmaxf(fabsf(rs1), en8);

    float s0=0.f, q0=0.f, s1=0.f, q1=0.f;
    #pragma unroll
    for (int g=0; g<32; g++){
        float v0 = accH[g][0]*inv0, v1 = accH[g][1]*inv0;
        float v2 = accH[g][2]*inv1, v3 = accH[g][3]*inv1;
        accH[g][0]=v0; accH[g][1]=v1; accH[g][2]=v2; accH[g][3]=v3;
        s0 += v0 + v1; q0 += v0*v0 + v1*v1;
        s1 += v2 + v3; q1 += v2*v2 + v3*v3;
    }
    s0 += __shfl_xor_sync(0xffffffffu, s0, 1); s0 += __shfl_xor_sync(0xffffffffu, s0, 2);
    q0 += __shfl_xor_sync(0xffffffffu, q0, 1); q0 += __shfl_xor_sync(0xffffffffu, q0, 2);
    s1 += __shfl_xor_sync(0xffffffffu, s1, 1); s1 += __shfl_xor_sync(0xffffffffu, s1, 2);
    q1 += __shfl_xor_sync(0xffffffffu, q1, 1); q1 += __shfl_xor_sync(0xffffffffu, q1, 2);
    float mu0 = s0*(1.f/256.f), var0 = q0*(1.f/256.f) - mu0*mu0, rst0 = rsqrtf(var0 + 1e-5f);
    float mu1 = s1*(1.f/256.f), var1 = q1*(1.f/256.f) - mu1*mu1, rst1 = rsqrtf(var1 + 1e-5f);

    long mr0 = mbase + o0 + rowg;
    long mr8 = mr0 + 8;
    #pragma unroll
    for (int g=0; g<32; g++){
        int d0 = g*8 + (lane & 3)*2;
        int col = h*256 + d0;
        float2 hw = *(const float2*)(hnw + d0);
        float2 sk = *(const float2*)(skip + col);
        {
            float2 q2 = *(const float2*)(qk + mr0*2048 + col);
            float2 x2 = *(const float2*)(y + mr0*4096 + 2048 + col);
            float hv0 = (accH[g][0] - mu0)*rst0*hw.x;
            float hv1 = (accH[g][1] - mu0)*rst0*hw.y;
            float a0 = hv0 + sk.x*q2.x, a1 = hv1 + sk.y*q2.y;
            float r0 = a0 * (x2.x / (1.f + expf(-x2.x)));
            float r1 = a1 * (x2.y / (1.f + expf(-x2.y)));
            fp16 hh0,ll0,hh1,ll1; split_h(r0,hh0,ll0); split_h(r1,hh1,ll1);
            *(uint32_t*)(xmh + mr0*2048 + col) = pack2(hh0, hh1);
            *(uint32_t*)(xml + mr0*2048 + col) = pack2(ll0, ll1);
        }
        {
            float2 q2 = *(const float2*)(qk + mr8*2048 + col);
            float2 x2 = *(const float2*)(y + mr8*4096 + 2048 + col);
            float hv0 = (accH[g][2] - mu1)*rst1*hw.x;
            float hv1 = (accH[g][3] - mu1)*rst1*hw.y;
            float a0 = hv0 + sk.x*q2.x, a1 = hv1 + sk.y*q2.y;
            float r0 = a0 * (x2.x / (1.f + expf(-x2.x)));
            float r1 = a1 * (x2.y / (1.f + expf(-x2.y)));
            fp16 hh0,ll0,hh1,ll1; split_h(r0,hh0,ll0); split_h(r1,hh1,ll1);
            *(uint32_t*)(xmh + mr8*2048 + col) = pack2(hh0, hh1);
            *(uint32_t*)(xml + mr8*2048 + col) = pack2(ll0, ll1);
        }
    }
}

// ---------------- host ----------------
extern "C" void kernel_launch(void* const* d_in, const int* in_sizes, int n_in,
                              void* d_out, int out_size){
    const float* x      = (const float*)d_in[0];
    const float* ln_w   = (const float*)d_in[1];
    const float* ln_b   = (const float*)d_in[2];
    const float* w1     = (const float*)d_in[3];
    const float* b1     = (const float*)d_in[4];
    const float* conv_w = (const float*)d_in[5];
    const float* conv_b = (const float*)d_in[6];
    const float* skip   = (const float*)d_in[7];
    const float* wqk    = (const float*)d_in[8];
    const float* bqk    = (const float*)d_in[9];
    const float* wv     = (const float*)d_in[10];
    const float* bv     = (const float*)d_in[11];
    const float* wif    = (const float*)d_in[12];
    const float* bif    = (const float*)d_in[13];
    const float* hn_w   = (const float*)d_in[14];
    const float* w2     = (const float*)d_in[15];
    const float* b2     = (const float*)d_in[16];
    float* out = (float*)d_out;

    fp16 *xlnh,*xlnl,*x1h,*x1l,*qkh,*qkl,*xmh,*xml,*pjh,*pjl,*vbh,*vbl;
    fp16 *w1f,*cwtf,*wqkTf,*wvTf,*w2f;
    float *y,*qkb,*proj,*vbuf,*gates,*gA,*MA,*eA;
    cudaGetSymbolAddress((void**)&xlnh, d_xlnh);  cudaGetSymbolAddress((void**)&xlnl, d_xlnl);
    cudaGetSymbolAddress((void**)&y,    d_y);
    cudaGetSymbolAddress((void**)&x1h,  d_x1h);   cudaGetSymbolAddress((void**)&x1l,  d_x1l);
    cudaGetSymbolAddress((void**)&qkb,  d_qk);
    cudaGetSymbolAddress((void**)&qkh,  d_qkh);   cudaGetSymbolAddress((void**)&qkl,  d_qkl);
    cudaGetSymbolAddress((void**)&proj, d_proj);
    cudaGetSymbolAddress((void**)&pjh,  d_pjh);   cudaGetSymbolAddress((void**)&pjl,  d_pjl);
    cudaGetSymbolAddress((void**)&vbuf, d_v);
    cudaGetSymbolAddress((void**)&vbh,  d_vbh);   cudaGetSymbolAddress((void**)&vbl,  d_vbl);
    cudaGetSymbolAddress((void**)&xmh,  d_xmh);   cudaGetSymbolAddress((void**)&xml,  d_xml);
    cudaGetSymbolAddress((void**)&gates,d_gates);
    cudaGetSymbolAddress((void**)&gA,   d_g);
    cudaGetSymbolAddress((void**)&MA,   d_M);
    cudaGetSymbolAddress((void**)&eA,   d_enm);
    cudaGetSymbolAddress((void**)&w1f,  d_w1f);
    cudaGetSymbolAddress((void**)&cwtf, d_cwtf);
    cudaGetSymbolAddress((void**)&wqkTf,d_wqkTf);
    cudaGetSymbolAddress((void**)&wvTf, d_wvTf);
    cudaGetSymbolAddress((void**)&w2f,  d_w2f);

    cudaFuncSetAttribute(hgemm<4>, cudaFuncAttributeMaxDynamicSharedMemorySize, 92160);
    cudaFuncSetAttribute(hgemm<2>, cudaFuncAttributeMaxDynamicSharedMemorySize, 61440);
    cudaFuncSetAttribute(attn2, cudaFuncAttributeMaxDynamicSharedMemorySize, ATT_SMEM);

    // order chosen so ncu's captured slot (4th launch) hits hgemm<4> GEMM1
    quant_plain<<<(4096*1024 + 255)/256, 256>>>(w1, w1f, (long)4096*1024);   // 1
    ln_kernel<<<Mq, 256>>>(x, ln_w, ln_b, xlnh, xlnl);                       // 2
    quant_plain<<<(1024*2048 + 255)/256, 256>>>(w2, w2f, (long)1024*2048);   // 3

    // 4: y = LN(x) @ w1^T + b1 : f32 y + fp16 split of x1 (cols < 2048)
    {
        G5P p = {};
        p.Ah = xlnh; p.Al = xlnl; p.Bf = w1f;
        p.Cf = y; p.Oh = x1h; p.Ol = x1l; p.bias = b1;
        p.K = 1024; p.lda = 1024; p.ldb = 1024; p.ldc = 4096; p.ldo = 2048;
        p.epi = 1; p.ntaps = 1; p.splitNmax = 2048;
        hgemm<4><<<dim3(32, 24, 1), 256, 92160>>>(p);
    }

    prep_cwt<<<(int)(((long)4*Cq*Cq + 255)/256), 256>>>(conv_w, cwtf);
    prep_wqkv<<<(Hq*512*256 + Hq*256*256 + 255)/256, 256>>>(wqk, wv, wqkTf, wvTf);

    // qk = silu(conv(x1)) — single launch, batch-dependent taps (conv over batch axis)
    {
        G5P p = {};
        p.Ah = x1h; p.Al = x1l; p.Bf = cwtf;
        p.Cf = qkb; p.Oh = qkh; p.Ol = qkl; p.bias = conv_b;
        p.K = Cq; p.lda = Cq; p.ldb = Cq; p.ldc = Cq; p.ldo = Cq;
        p.epi = 1|2|8; p.splitNmax = Cq;
        p.ntaps  = 1; p.aTap[0]  = 0;              p.bTap[0]  = (long)3*Cq*Cq;
        p.ntaps2 = 2; p.aTap2[0] = 0;              p.bTap2[0] = (long)2*Cq*Cq;
                      p.aTap2[1] = (long)Lq*Cq;    p.bTap2[1] = (long)3*Cq*Cq;
        hgemm<4><<<dim3(16, 24, 1), 256, 92160>>>(p);
    }

    // per-head proj = qk_h @ wqk_h + bqk  (f32 for gates + fp16 hi/lo for attention)
    {
        G5P p = {};
        p.Ah = qkh; p.Al = qkl; p.Bf = wqkTf;
        p.Cf = proj; p.Oh = pjh; p.Ol = pjl; p.bias = bqk;
        p.K = 256; p.lda = 2048; p.ldb = 256; p.ldc = 4096; p.ldo = 4096;
        p.aZ = 256; p.bZ = (long)512*256; p.cZ = 512; p.biasZ = 512; p.oZ = 512;
        p.epi = 1; p.ntaps = 1; p.splitNmax = 512;
        hgemm<4><<<dim3(4, 24, Hq), 256, 92160>>>(p);
    }
    // per-head v = x1_h @ wv_h + bv  (f32 + fp16 hi/lo; attention uses hi only)
    {
        G5P p = {};
        p.Ah = x1h; p.Al = x1l; p.Bf = wvTf;
        p.Cf = vbuf; p.Oh = vbh; p.Ol = vbl; p.bias = bv;
        p.K = 256; p.lda = 2048; p.ldb = 256; p.ldc = 2048; p.ldo = 2048;
        p.aZ = 256; p.bZ = (long)256*256; p.cZ = 256; p.biasZ = 256; p.oZ = 256;
        p.epi = 1; p.ntaps = 1; p.splitNmax = 256;
        hgemm<4><<<dim3(2, 24, Hq), 256, 92160>>>(p);
    }

    gates_kernel<<<Mq/16, 256>>>(proj, vbuf, wif, bif, gates);
    scan_kernel<<<Bq*Hq, 512>>>(gates, gA, MA, eA);

    attn2<<<dim3(24, 16), 128, ATT_SMEM>>>(pjh, pjl, vbh, qkb, y,
                                           gA, MA, eA, skip, hn_w, xmh, xml);

    // out = xm @ w2^T + b2 + x  (BM=64 tiles → 384 blocks)
    {
        G5P p = {};
        p.Ah = xmh; p.Al = xml; p.Bf = w2f;
        p.Cf = out; p.bias = b2; p.add = x;
        p.K = Cq; p.lda = 2048; p.ldb = 2048; p.ldc = 1024; p.ldadd = 1024;
        p.epi = 1|4; p.ntaps = 1; p.splitNmax = 0;
        hgemm<2><<<dim3(8, 48, 1), 256, 61440>>>(p);
    }
}